// round 9
// baseline (speedup 1.0000x reference)
#include <cuda_runtime.h>
#include <cuda_fp16.h>

#define BATCH 32
#define CDIM  256
#define LDIM  1024

// ---------------------------------------------------------------------------
// Global scratch
// q packed: d_qpk [b][m][i], m=c/2, uint2=(hi2,lo2), hi2=(h(q[2m][i]),h(q[2m+1][i]))
// k planes: d_kpl [b][plane][c][j2], plane 0=hi, 1=lo, uint=half2 along j
// v/std packed: [b][c][j2] half2 ; P: [b][i][j2] half2 ; bias dense fp32
// ---------------------------------------------------------------------------
__device__ uint2    d_qpk[(size_t)BATCH * (CDIM / 2) * LDIM];         // 32 MiB
__device__ unsigned d_kpl[(size_t)BATCH * 2 * CDIM * (LDIM / 2)];     // 32 MiB
__device__ unsigned d_vpk[(size_t)BATCH * CDIM * (LDIM / 2)];         // 16 MiB
__device__ unsigned d_spk[(size_t)BATCH * CDIM * (LDIM / 2)];         // 16 MiB
__device__ unsigned d_Ph [(size_t)BATCH * LDIM * (LDIM / 2)];         // 64 MiB
__device__ float    d_bias[(size_t)LDIM * LDIM];                      //  4 MiB

__device__ __forceinline__ unsigned pk2(__half a, __half b) {
    __half2 t = __halves2half2(a, b);
    return *reinterpret_cast<unsigned*>(&t);
}

__device__ __forceinline__ void mma16(float* c,
                                      unsigned a0, unsigned a1, unsigned a2, unsigned a3,
                                      unsigned b0, unsigned b1) {
    asm volatile(
        "mma.sync.aligned.m16n8k16.row.col.f32.f16.f16.f32 "
        "{%0,%1,%2,%3}, {%4,%5,%6,%7}, {%8,%9}, {%0,%1,%2,%3};\n"
        : "+f"(c[0]), "+f"(c[1]), "+f"(c[2]), "+f"(c[3])
        : "r"(a0), "r"(a1), "r"(a2), "r"(a3), "r"(b0), "r"(b1));
}

__device__ __forceinline__ void ldsm4(unsigned& r0, unsigned& r1,
                                      unsigned& r2, unsigned& r3, unsigned a) {
    asm volatile("ldmatrix.sync.aligned.m8n8.x4.shared.b16 {%0,%1,%2,%3}, [%4];"
                 : "=r"(r0), "=r"(r1), "=r"(r2), "=r"(r3) : "r"(a));
}

__device__ __forceinline__ void ldsm4t(unsigned& r0, unsigned& r1,
                                       unsigned& r2, unsigned& r3, unsigned a) {
    asm volatile("ldmatrix.sync.aligned.m8n8.x4.trans.shared.b16 {%0,%1,%2,%3}, [%4];"
                 : "=r"(r0), "=r"(r1), "=r"(r2), "=r"(r3) : "r"(a));
}

__device__ __forceinline__ void cp16(unsigned dst, const void* src) {
    asm volatile("cp.async.cg.shared.global [%0], [%1], 16;" :: "r"(dst), "l"(src));
}
#define CP_COMMIT() asm volatile("cp.async.commit_group;")
#define CP_WAIT(N)  asm volatile("cp.async.wait_group %0;" :: "n"(N))

// ---------------------------------------------------------------------------
// Pack kernels
// ---------------------------------------------------------------------------
__global__ void pack_q(const float* __restrict__ q) {
    int gid = blockIdx.x * 256 + threadIdx.x;     // over B * 128 * 1024 (m,i)
    int b   = gid >> 17;
    int rem = gid & 131071;
    int m   = rem >> 10;
    int i   = rem & 1023;
    size_t src = (size_t)b * CDIM * LDIM + (size_t)(2 * m) * LDIM + i;
    float x0 = q[src], x1 = q[src + LDIM];
    __half h0 = __float2half_rn(x0), h1 = __float2half_rn(x1);
    __half l0 = __float2half_rn(x0 - __half2float(h0));
    __half l1 = __float2half_rn(x1 - __half2float(h1));
    d_qpk[gid] = make_uint2(pk2(h0, h1), pk2(l0, l1));
}

__global__ void pack_kvs(const float* __restrict__ k, const float* __restrict__ v,
                         const float* __restrict__ sd) {
    int gid = blockIdx.x * 256 + threadIdx.x;     // over B*C*(L/2), [b][c][j2]
    int b   = gid >> 17;
    int wit = gid & 131071;
    size_t src = (size_t)gid * 2;

    float2 kk = *(const float2*)(k + src);
    __half h0 = __float2half_rn(kk.x), h1 = __float2half_rn(kk.y);
    __half l0 = __float2half_rn(kk.x - __half2float(h0));
    __half l1 = __float2half_rn(kk.y - __half2float(h1));
    d_kpl[(size_t)b * 262144 + wit]          = pk2(h0, h1);
    d_kpl[(size_t)b * 262144 + 131072 + wit] = pk2(l0, l1);

    float2 t = *(const float2*)(v + src);
    d_vpk[gid] = pk2(__float2half_rn(t.x), __float2half_rn(t.y));
    float2 u = *(const float2*)(sd + src);
    d_spk[gid] = pk2(__float2half_rn(u.x), __float2half_rn(u.y));
}

__global__ void bias_kernel(const float* __restrict__ table,
                            const int* __restrict__ ridx) {
    int i = blockIdx.x * blockDim.x + threadIdx.x;
    d_bias[i] = table[ridx[i]];
}

// ---------------------------------------------------------------------------
// Kernel 1: scores = Q^T K + bias (fp16x2 3-pass), softmax, P -> half2.
// CTA: 32 i x 1024 j, 512 threads = 16 warps, warp tile 32i x 64j.
// c chunks of 16, 3-buffer cp.async pipeline, ONE sync per chunk.
// K smem: per buf 2 planes x 16 rows x 2064B (pad 16B: conflict-free ldsm.trans)
// B frags via ldmatrix.x4.trans, A frags via ldmatrix.x4.
// ---------------------------------------------------------------------------
#define T1 512
#define KROWB 2064
#define KPLANE (16 * KROWB)          // 33024
#define SC_K(buf)   ((buf) * (2 * KPLANE))
#define SC_QH(buf)  (3 * 2 * KPLANE + (buf) * 3072)
#define SC_QL(buf)  (SC_QH(buf) + 1536)
#define SC_RED      (3 * 2 * KPLANE + 3 * 3072)
#define SC_TOTAL    (SC_RED + 32 * 16 * 4)

__global__ void __launch_bounds__(T1)
scores_kernel(void) {
    extern __shared__ unsigned char smraw[];
    const unsigned sbase = (unsigned)__cvta_generic_to_shared(smraw);

    const int b    = blockIdx.y;
    const int i0   = blockIdx.x * 32;
    const int tid  = threadIdx.x;
    const int warp = tid >> 5;
    const int lane = tid & 31;
    const int g    = lane >> 2;
    const int tig  = lane & 3;
    const int j0w  = warp * 64;

    const uint2*    gq = d_qpk + (size_t)b * (CDIM / 2) * LDIM;
    const unsigned* gk = d_kpl + (size_t)b * 262144;

    float acc[2][8][4];
#pragma unroll
    for (int it = 0; it < 2; it++)
#pragma unroll
        for (int jt = 0; jt < 8; jt++)
#pragma unroll
            for (int f = 0; f < 4; f++) acc[it][jt][f] = 0.f;

#define SC_STAGE(CC, BUF)                                                     \
    {                                                                         \
        _Pragma("unroll")                                                     \
        for (int t = 0; t < 8; t++) {                                         \
            int idx   = tid + t * T1;                                         \
            int plane = idx >> 11;                                            \
            int row   = (idx >> 7) & 15;                                      \
            int col   = idx & 127;                                            \
            cp16(sbase + SC_K(BUF) + plane * KPLANE + row * KROWB + col * 16, \
                 gk + ((size_t)plane * 256 + (CC) * 16 + row) * 512 + col * 4);\
        }                                                                     \
        if (tid < 256) {                                                      \
            int m = tid >> 5, ii = tid & 31;                                  \
            uint2 qv = gq[(size_t)((CC) * 16 + m * 2) * LDIM / 2 + i0 + ii];  \
            *(unsigned*)(smraw + SC_QH(BUF) + (ii * 12 + m) * 4) = qv.x;      \
            *(unsigned*)(smraw + SC_QL(BUF) + (ii * 12 + m) * 4) = qv.y;      \
        }                                                                     \
        CP_COMMIT();                                                          \
    }

    SC_STAGE(0, 0);
    SC_STAGE(1, 1);

    const unsigned a_row  = lane & 15;
    const unsigned a_sel  = (lane >> 4) * 16;
    const unsigned b_crow = lane & 15;
    const unsigned b_joff = (lane >> 4) * 8;

    for (int cc = 0; cc < 16; cc++) {
        if (cc < 15) { CP_WAIT(1); } else { CP_WAIT(0); }
        __syncthreads();
        const int buf = cc % 3;
        if (cc + 2 < 16) SC_STAGE(cc + 2, (cc + 2) % 3);

        unsigned ah[2][4], al[2][4];
#pragma unroll
        for (int it = 0; it < 2; it++) {
            ldsm4(ah[it][0], ah[it][1], ah[it][2], ah[it][3],
                  sbase + SC_QH(buf) + (it * 16 + a_row) * 48 + a_sel);
            ldsm4(al[it][0], al[it][1], al[it][2], al[it][3],
                  sbase + SC_QL(buf) + (it * 16 + a_row) * 48 + a_sel);
        }
#pragma unroll
        for (int jh = 0; jh < 2; jh++) {
            unsigned bh0[4], bh1[4], bl0[4], bl1[4];
#pragma unroll
            for (int p = 0; p < 2; p++) {
                unsigned joff = (j0w + jh * 32 + p * 16 + b_joff) * 2;
                unsigned rb   = sbase + SC_K(buf) + b_crow * KROWB + joff;
                ldsm4t(bh0[2 * p], bh1[2 * p], bh0[2 * p + 1], bh1[2 * p + 1], rb);
                ldsm4t(bl0[2 * p], bl1[2 * p], bl0[2 * p + 1], bl1[2 * p + 1],
                       rb + KPLANE);
            }
            // pass 1: hi*hi
#pragma unroll
            for (int j4 = 0; j4 < 4; j4++)
#pragma unroll
                for (int it = 0; it < 2; it++)
                    mma16(acc[it][jh * 4 + j4], ah[it][0], ah[it][1], ah[it][2], ah[it][3],
                          bh0[j4], bh1[j4]);
            // pass 2: hi*lo
#pragma unroll
            for (int j4 = 0; j4 < 4; j4++)
#pragma unroll
                for (int it = 0; it < 2; it++)
                    mma16(acc[it][jh * 4 + j4], ah[it][0], ah[it][1], ah[it][2], ah[it][3],
                          bl0[j4], bl1[j4]);
            // pass 3: lo*hi
#pragma unroll
            for (int j4 = 0; j4 < 4; j4++)
#pragma unroll
                for (int it = 0; it < 2; it++)
                    mma16(acc[it][jh * 4 + j4], al[it][0], al[it][1], al[it][2], al[it][3],
                          bh0[j4], bh1[j4]);
        }
    }

    float* red = (float*)(smraw + SC_RED);

    // ---- add bias ----
#pragma unroll
    for (int it = 0; it < 2; it++)
#pragma unroll
        for (int rr = 0; rr < 2; rr++) {
            int rowl = it * 16 + g + rr * 8;
            const float* brow = d_bias + (size_t)(i0 + rowl) * LDIM + j0w + 2 * tig;
#pragma unroll
            for (int jt = 0; jt < 8; jt++) {
                float2 bv = *(const float2*)(brow + jt * 8);
                acc[it][jt][rr * 2]     += bv.x;
                acc[it][jt][rr * 2 + 1] += bv.y;
            }
        }

    // ---- row max ----
    float mrow[2][2];
#pragma unroll
    for (int it = 0; it < 2; it++)
#pragma unroll
        for (int rr = 0; rr < 2; rr++) {
            float m = -3.4e38f;
#pragma unroll
            for (int jt = 0; jt < 8; jt++) {
                m = fmaxf(m, acc[it][jt][rr * 2]);
                m = fmaxf(m, acc[it][jt][rr * 2 + 1]);
            }
            m = fmaxf(m, __shfl_xor_sync(0xffffffffu, m, 1));
            m = fmaxf(m, __shfl_xor_sync(0xffffffffu, m, 2));
            if (tig == 0) red[(it * 16 + g + rr * 8) * 16 + warp] = m;
        }
    __syncthreads();
#pragma unroll
    for (int it = 0; it < 2; it++)
#pragma unroll
        for (int rr = 0; rr < 2; rr++) {
            int rowl = it * 16 + g + rr * 8;
            float m = red[rowl * 16];
#pragma unroll
            for (int w = 1; w < 16; w++) m = fmaxf(m, red[rowl * 16 + w]);
            mrow[it][rr] = m;
        }
    __syncthreads();

    // ---- exp + row sum ----
#pragma unroll
    for (int it = 0; it < 2; it++)
#pragma unroll
        for (int rr = 0; rr < 2; rr++) {
            float s = 0.f;
#pragma unroll
            for (int jt = 0; jt < 8; jt++) {
                float p0 = __expf(acc[it][jt][rr * 2]     - mrow[it][rr]);
                float p1 = __expf(acc[it][jt][rr * 2 + 1] - mrow[it][rr]);
                acc[it][jt][rr * 2]     = p0;
                acc[it][jt][rr * 2 + 1] = p1;
                s += p0 + p1;
            }
            s += __shfl_xor_sync(0xffffffffu, s, 1);
            s += __shfl_xor_sync(0xffffffffu, s, 2);
            if (tig == 0) red[(it * 16 + g + rr * 8) * 16 + warp] = s;
        }
    __syncthreads();

    unsigned* Pb = d_Ph + ((size_t)b * LDIM + i0) * (LDIM / 2);
#pragma unroll
    for (int it = 0; it < 2; it++)
#pragma unroll
        for (int rr = 0; rr < 2; rr++) {
            int rowl = it * 16 + g + rr * 8;
            float s = red[rowl * 16];
#pragma unroll
            for (int w = 1; w < 16; w++) s += red[rowl * 16 + w];
            float inv = 1.0f / s;
            unsigned* prow = Pb + (size_t)rowl * (LDIM / 2) + j0w / 2 + tig;
#pragma unroll
            for (int jt = 0; jt < 8; jt++) {
                __half2 h = __floats2half2_rn(acc[it][jt][rr * 2] * inv,
                                              acc[it][jt][rr * 2 + 1] * inv);
                prow[jt * 4] = *reinterpret_cast<unsigned*>(&h);
            }
        }
}

// ---------------------------------------------------------------------------
// Kernel 2: V = P @ v^T, SD = P @ std^T, fp16 m16n8k16, ldmatrix everywhere.
// CTA tile: 128i x 128c, 512 threads = 16 warps (4 wi x 4 wc), j chunk 64.
// 3-buffer cp.async pipeline, ONE sync per chunk.
// ---------------------------------------------------------------------------
#define T2  512
#define OSW 36   // uints per smem row (144 B)

#define OC_PS(buf)  ((buf) * (3 * 128 * OSW * 4))
#define OC_VS(buf)  (OC_PS(buf) + 128 * OSW * 4)
#define OC_SS(buf)  (OC_PS(buf) + 2 * 128 * OSW * 4)
#define OC_TOTAL    (3 * 3 * 128 * OSW * 4)

__global__ void __launch_bounds__(T2)
out_kernel(float* __restrict__ out) {
    extern __shared__ unsigned char smraw2[];
    const unsigned sbase = (unsigned)__cvta_generic_to_shared(smraw2);

    const int b    = blockIdx.z;
    const int i0   = blockIdx.x * 128;
    const int c0   = blockIdx.y * 128;
    const int tid  = threadIdx.x;
    const int warp = tid >> 5;
    const int lane = tid & 31;
    const int g    = lane >> 2;
    const int tig  = lane & 3;
    const int wi   = warp & 3;
    const int wc   = warp >> 2;

    const unsigned* Pb = d_Ph + ((size_t)b * LDIM + i0) * (LDIM / 2);
    const unsigned* vb = d_vpk + ((size_t)b * CDIM + c0) * (LDIM / 2);
    const unsigned* sb = d_spk + ((size_t)b * CDIM + c0) * (LDIM / 2);

    float aV[2][4][4], aS[2][4][4];
#pragma unroll
    for (int it = 0; it < 2; it++)
#pragma unroll
        for (int nt = 0; nt < 4; nt++)
#pragma unroll
            for (int f = 0; f < 4; f++) { aV[it][nt][f] = 0.f; aS[it][nt][f] = 0.f; }

#define OC_STAGE(JC, BUF)                                                     \
    {                                                                         \
        _Pragma("unroll")                                                     \
        for (int t = 0; t < 2; t++) {                                         \
            int idx  = tid + t * T2;                                          \
            int row  = idx >> 3;                                              \
            int col4 = idx & 7;                                               \
            unsigned soff = row * (OSW * 4) + col4 * 16;                      \
            size_t   goff = (size_t)row * (LDIM / 2) + (JC) * 32 + col4 * 4;  \
            cp16(sbase + OC_PS(BUF) + soff, Pb + goff);                       \
            cp16(sbase + OC_VS(BUF) + soff, vb + goff);                       \
            cp16(sbase + OC_SS(BUF) + soff, sb + goff);                       \
        }                                                                     \
        CP_COMMIT();                                                          \
    }

    OC_STAGE(0, 0);
    OC_STAGE(1, 1);

    const unsigned a_row = (lane & 15);
    const unsigned a_col = (lane >> 4) * 16;
    const unsigned b_row = ((lane >> 4) & 1) * 8 + (lane & 7);
    const unsigned b_col = ((lane >> 3) & 1) * 16;

    for (int jc = 0; jc < 16; jc++) {
        if (jc < 15) { CP_WAIT(1); } else { CP_WAIT(0); }
        __syncthreads();
        const int buf = jc % 3;
        if (jc + 2 < 16) OC_STAGE(jc + 2, (jc + 2) % 3);

#pragma unroll
        for (int kb = 0; kb < 4; kb++) {
            unsigned a0[2], a1[2], a2[2], a3[2];
#pragma unroll
            for (int it = 0; it < 2; it++)
                ldsm4(a0[it], a1[it], a2[it], a3[it],
                      sbase + OC_PS(buf) +
                      (wi * 32 + it * 16 + a_row) * (OSW * 4) + kb * 32 + a_col);

            unsigned bv0[4], bv1[4], bs0[4], bs1[4];
#pragma unroll
            for (int nh = 0; nh < 2; nh++) {
                unsigned roff = (wc * 32 + nh * 16 + b_row) * (OSW * 4) + kb * 32 + b_col;
                ldsm4(bv0[2 * nh], bv1[2 * nh], bv0[2 * nh + 1], bv1[2 * nh + 1],
                      sbase + OC_VS(buf) + roff);
                ldsm4(bs0[2 * nh], bs1[2 * nh], bs0[2 * nh + 1], bs1[2 * nh + 1],
                      sbase + OC_SS(buf) + roff);
            }
#pragma unroll
            for (int nt = 0; nt < 4; nt++)
#pragma unroll
                for (int it = 0; it < 2; it++) {
                    mma16(aV[it][nt], a0[it], a1[it], a2[it], a3[it], bv0[nt], bv1[nt]);
                    mma16(aS[it][nt], a0[it], a1[it], a2[it], a3[it], bs0[nt], bs1[nt]);
                }
        }
    }

    const size_t base  = (size_t)b * CDIM * LDIM;
    const size_t sdoff = (size_t)BATCH * CDIM * LDIM;
#pragma unroll
    for (int it = 0; it < 2; it++)
#pragma unroll
        for (int nt = 0; nt < 4; nt++)
#pragma unroll
            for (int rr = 0; rr < 2; rr++) {
                int i = i0 + wi * 32 + it * 16 + g + rr * 8;
#pragma unroll
                for (int ff = 0; ff < 2; ff++) {
                    int c = c0 + wc * 32 + nt * 8 + 2 * tig + ff;
                    size_t o = base + (size_t)c * LDIM + i;
                    out[o]         = aV[it][nt][rr * 2 + ff];
                    out[o + sdoff] = aS[it][nt][rr * 2 + ff];
                }
            }
}

// ---------------------------------------------------------------------------
extern "C" void kernel_launch(void* const* d_in, const int* in_sizes, int n_in,
                              void* d_out, int out_size) {
    const float* q     = (const float*)d_in[0];
    const float* k     = (const float*)d_in[1];
    const float* v     = (const float*)d_in[2];
    const float* sd    = (const float*)d_in[3];
    const float* table = (const float*)d_in[4];
    const int*   ridx  = (const int*)d_in[5];
    float* out = (float*)d_out;

    cudaFuncSetAttribute(scores_kernel, cudaFuncAttributeMaxDynamicSharedMemorySize, SC_TOTAL);
    cudaFuncSetAttribute(out_kernel,    cudaFuncAttributeMaxDynamicSharedMemorySize, OC_TOTAL);

    pack_q  <<<(BATCH * (CDIM / 2) * LDIM) / 256, 256>>>(q);
    pack_kvs<<<(BATCH * CDIM * (LDIM / 2)) / 256, 256>>>(k, v, sd);
    bias_kernel<<<(LDIM * LDIM) / 256, 256>>>(table, ridx);
    scores_kernel<<<dim3(LDIM / 32, BATCH), T1, SC_TOTAL>>>();
    out_kernel<<<dim3(LDIM / 128, CDIM / 128, BATCH), T2, OC_TOTAL>>>(out);
}

// round 10
// speedup vs baseline: 1.2323x; 1.2323x over previous
#include <cuda_runtime.h>
#include <cuda_fp16.h>

#define BATCH 32
#define CDIM  256
#define LDIM  1024

// ---------------------------------------------------------------------------
// Global scratch
// q packed: d_qpk [b][m][i], m=c/2, uint2=(hi2,lo2), hi2=(h(q[2m][i]),h(q[2m+1][i]))
// k planes: d_kpl [b][plane][c][j2], plane 0=hi, 1=lo, uint=half2 along j
// v/std packed: [b][c][j2] half2 ; P: [b][i][j2] half2 ; bias dense fp32
// ---------------------------------------------------------------------------
__device__ uint2    d_qpk[(size_t)BATCH * (CDIM / 2) * LDIM];         // 32 MiB
__device__ unsigned d_kpl[(size_t)BATCH * 2 * CDIM * (LDIM / 2)];     // 32 MiB
__device__ unsigned d_vpk[(size_t)BATCH * CDIM * (LDIM / 2)];         // 16 MiB
__device__ unsigned d_spk[(size_t)BATCH * CDIM * (LDIM / 2)];         // 16 MiB
__device__ unsigned d_Ph [(size_t)BATCH * LDIM * (LDIM / 2)];         // 64 MiB
__device__ float    d_bias[(size_t)LDIM * LDIM];                      //  4 MiB

__device__ __forceinline__ unsigned pk2(__half a, __half b) {
    __half2 t = __halves2half2(a, b);
    return *reinterpret_cast<unsigned*>(&t);
}

__device__ __forceinline__ void mma16(float* c,
                                      unsigned a0, unsigned a1, unsigned a2, unsigned a3,
                                      unsigned b0, unsigned b1) {
    asm volatile(
        "mma.sync.aligned.m16n8k16.row.col.f32.f16.f16.f32 "
        "{%0,%1,%2,%3}, {%4,%5,%6,%7}, {%8,%9}, {%0,%1,%2,%3};\n"
        : "+f"(c[0]), "+f"(c[1]), "+f"(c[2]), "+f"(c[3])
        : "r"(a0), "r"(a1), "r"(a2), "r"(a3), "r"(b0), "r"(b1));
}

__device__ __forceinline__ void ldsm4(unsigned& r0, unsigned& r1,
                                      unsigned& r2, unsigned& r3, unsigned a) {
    asm volatile("ldmatrix.sync.aligned.m8n8.x4.shared.b16 {%0,%1,%2,%3}, [%4];"
                 : "=r"(r0), "=r"(r1), "=r"(r2), "=r"(r3) : "r"(a));
}

__device__ __forceinline__ void ldsm4t(unsigned& r0, unsigned& r1,
                                       unsigned& r2, unsigned& r3, unsigned a) {
    asm volatile("ldmatrix.sync.aligned.m8n8.x4.trans.shared.b16 {%0,%1,%2,%3}, [%4];"
                 : "=r"(r0), "=r"(r1), "=r"(r2), "=r"(r3) : "r"(a));
}

__device__ __forceinline__ void cp16(unsigned dst, const void* src) {
    asm volatile("cp.async.cg.shared.global [%0], [%1], 16;" :: "r"(dst), "l"(src));
}
#define CP_COMMIT() asm volatile("cp.async.commit_group;")
#define CP_WAIT(N)  asm volatile("cp.async.wait_group %0;" :: "n"(N))

// ---------------------------------------------------------------------------
// Pack kernels
// ---------------------------------------------------------------------------
__global__ void pack_q(const float* __restrict__ q) {
    int gid = blockIdx.x * 256 + threadIdx.x;     // over B * 128 * 1024 (m,i)
    int b   = gid >> 17;
    int rem = gid & 131071;
    int m   = rem >> 10;
    int i   = rem & 1023;
    size_t src = (size_t)b * CDIM * LDIM + (size_t)(2 * m) * LDIM + i;
    float x0 = q[src], x1 = q[src + LDIM];
    __half h0 = __float2half_rn(x0), h1 = __float2half_rn(x1);
    __half l0 = __float2half_rn(x0 - __half2float(h0));
    __half l1 = __float2half_rn(x1 - __half2float(h1));
    d_qpk[gid] = make_uint2(pk2(h0, h1), pk2(l0, l1));
}

__global__ void pack_kvs(const float* __restrict__ k, const float* __restrict__ v,
                         const float* __restrict__ sd) {
    int gid = blockIdx.x * 256 + threadIdx.x;     // over B*C*(L/2), [b][c][j2]
    int b   = gid >> 17;
    int wit = gid & 131071;
    size_t src = (size_t)gid * 2;

    float2 kk = *(const float2*)(k + src);
    __half h0 = __float2half_rn(kk.x), h1 = __float2half_rn(kk.y);
    __half l0 = __float2half_rn(kk.x - __half2float(h0));
    __half l1 = __float2half_rn(kk.y - __half2float(h1));
    d_kpl[(size_t)b * 262144 + wit]          = pk2(h0, h1);
    d_kpl[(size_t)b * 262144 + 131072 + wit] = pk2(l0, l1);

    float2 t = *(const float2*)(v + src);
    d_vpk[gid] = pk2(__float2half_rn(t.x), __float2half_rn(t.y));
    float2 u = *(const float2*)(sd + src);
    d_spk[gid] = pk2(__float2half_rn(u.x), __float2half_rn(u.y));
}

__global__ void bias_kernel(const float* __restrict__ table,
                            const int* __restrict__ ridx) {
    int i = blockIdx.x * blockDim.x + threadIdx.x;
    d_bias[i] = table[ridx[i]];
}

// ---------------------------------------------------------------------------
// Kernel 1: scores = Q^T K + bias (fp16x2 3-pass), softmax, P -> half2.
// R8 pipeline skeleton (2 buffers, stage at loop bottom, 2 syncs/chunk).
// ONLY change vs R8: K staged as split hi/lo planes, B-frags via ldmatrix.trans
// (8 LDSM replace 32 LDS.64 per warp-chunk). Row pad 2064B -> conflict-free.
// ---------------------------------------------------------------------------
#define T1 512
#define KROWB 2064
#define KPLANE (16 * KROWB)          // 33024 bytes: 16 c-rows x 1024 j halves
#define SC_K(buf)   ((buf) * (2 * KPLANE))
#define SC_QH(buf)  (2 * 2 * KPLANE + (buf) * 3072)
#define SC_QL(buf)  (SC_QH(buf) + 1536)
#define SC_RED      (2 * 2 * KPLANE + 2 * 3072)
#define SC_TOTAL    (SC_RED + 32 * 16 * 4)

__global__ void __launch_bounds__(T1)
scores_kernel(void) {
    extern __shared__ unsigned char smraw[];
    const unsigned sbase = (unsigned)__cvta_generic_to_shared(smraw);

    const int b    = blockIdx.y;
    const int i0   = blockIdx.x * 32;
    const int tid  = threadIdx.x;
    const int warp = tid >> 5;
    const int lane = tid & 31;
    const int g    = lane >> 2;
    const int tig  = lane & 3;
    const int j0w  = warp * 64;

    const uint2*    gq = d_qpk + (size_t)b * (CDIM / 2) * LDIM;
    const unsigned* gk = d_kpl + (size_t)b * 262144;

    float acc[2][8][4];
#pragma unroll
    for (int it = 0; it < 2; it++)
#pragma unroll
        for (int jt = 0; jt < 8; jt++)
#pragma unroll
            for (int f = 0; f < 4; f++) acc[it][jt][f] = 0.f;

    // stage chunk CC (16 c-rows, both planes) into buffer BUF
#define SC_STAGE(CC, BUF)                                                      \
    {                                                                          \
        _Pragma("unroll")                                                      \
        for (int t = 0; t < 8; t++) {                                          \
            int idx   = tid + t * T1;                                          \
            int plane = idx >> 11;                                             \
            int row   = (idx >> 7) & 15;                                       \
            int col   = idx & 127;                                             \
            cp16(sbase + SC_K(BUF) + plane * KPLANE + row * KROWB + col * 16,  \
                 gk + ((size_t)plane * 256 + (CC) * 16 + row) * 512 + col * 4);\
        }                                                                      \
        if (tid < 256) {                                                       \
            int m = tid >> 5, ii = tid & 31;                                   \
            uint2 qv = gq[(size_t)((CC) * 8 + m) * LDIM + i0 + ii];            \
            *(unsigned*)(smraw + SC_QH(BUF) + (ii * 12 + m) * 4) = qv.x;       \
            *(unsigned*)(smraw + SC_QL(BUF) + (ii * 12 + m) * 4) = qv.y;       \
        }                                                                      \
        CP_COMMIT();                                                           \
    }

    SC_STAGE(0, 0);
    SC_STAGE(1, 1);

    const unsigned a_row  = lane & 15;
    const unsigned a_sel  = (lane >> 4) * 16;
    const unsigned b_crow = lane & 15;            // k row within chunk
    const unsigned b_joff = (lane >> 4) * 8;      // +8 j for upper 16 lanes

    for (int cc = 0; cc < 16; cc++) {
        if (cc < 15) { CP_WAIT(1); } else { CP_WAIT(0); }
        __syncthreads();

        const int buf = cc & 1;
        // A fragments via ldmatrix.x4 (hi and lo)
        unsigned ah[2][4], al[2][4];
#pragma unroll
        for (int it = 0; it < 2; it++) {
            ldsm4(ah[it][0], ah[it][1], ah[it][2], ah[it][3],
                  sbase + SC_QH(buf) + (it * 16 + a_row) * 48 + a_sel);
            ldsm4(al[it][0], al[it][1], al[it][2], al[it][3],
                  sbase + SC_QL(buf) + (it * 16 + a_row) * 48 + a_sel);
        }
#pragma unroll
        for (int jh = 0; jh < 2; jh++) {
            unsigned bh0[4], bh1[4], bl0[4], bl1[4];
#pragma unroll
            for (int p = 0; p < 2; p++) {
                unsigned joff = (j0w + jh * 32 + p * 16 + b_joff) * 2;
                unsigned rb   = sbase + SC_K(buf) + b_crow * KROWB + joff;
                ldsm4t(bh0[2 * p], bh1[2 * p], bh0[2 * p + 1], bh1[2 * p + 1], rb);
                ldsm4t(bl0[2 * p], bl1[2 * p], bl0[2 * p + 1], bl1[2 * p + 1],
                       rb + KPLANE);
            }
            // pass 1: hi*hi
#pragma unroll
            for (int j4 = 0; j4 < 4; j4++)
#pragma unroll
                for (int it = 0; it < 2; it++)
                    mma16(acc[it][jh * 4 + j4], ah[it][0], ah[it][1], ah[it][2], ah[it][3],
                          bh0[j4], bh1[j4]);
            // pass 2: hi*lo
#pragma unroll
            for (int j4 = 0; j4 < 4; j4++)
#pragma unroll
                for (int it = 0; it < 2; it++)
                    mma16(acc[it][jh * 4 + j4], ah[it][0], ah[it][1], ah[it][2], ah[it][3],
                          bl0[j4], bl1[j4]);
            // pass 3: lo*hi
#pragma unroll
            for (int j4 = 0; j4 < 4; j4++)
#pragma unroll
                for (int it = 0; it < 2; it++)
                    mma16(acc[it][jh * 4 + j4], al[it][0], al[it][1], al[it][2], al[it][3],
                          bh0[j4], bh1[j4]);
        }
        __syncthreads();
        if (cc + 2 < 16) SC_STAGE(cc + 2, buf);
    }

    float* red = (float*)(smraw + SC_RED);

    // ---- add bias ----
#pragma unroll
    for (int it = 0; it < 2; it++)
#pragma unroll
        for (int rr = 0; rr < 2; rr++) {
            int rowl = it * 16 + g + rr * 8;
            const float* brow = d_bias + (size_t)(i0 + rowl) * LDIM + j0w + 2 * tig;
#pragma unroll
            for (int jt = 0; jt < 8; jt++) {
                float2 bv = *(const float2*)(brow + jt * 8);
                acc[it][jt][rr * 2]     += bv.x;
                acc[it][jt][rr * 2 + 1] += bv.y;
            }
        }

    // ---- row max ----
    float mrow[2][2];
#pragma unroll
    for (int it = 0; it < 2; it++)
#pragma unroll
        for (int rr = 0; rr < 2; rr++) {
            float m = -3.4e38f;
#pragma unroll
            for (int jt = 0; jt < 8; jt++) {
                m = fmaxf(m, acc[it][jt][rr * 2]);
                m = fmaxf(m, acc[it][jt][rr * 2 + 1]);
            }
            m = fmaxf(m, __shfl_xor_sync(0xffffffffu, m, 1));
            m = fmaxf(m, __shfl_xor_sync(0xffffffffu, m, 2));
            if (tig == 0) red[(it * 16 + g + rr * 8) * 16 + warp] = m;
        }
    __syncthreads();
#pragma unroll
    for (int it = 0; it < 2; it++)
#pragma unroll
        for (int rr = 0; rr < 2; rr++) {
            int rowl = it * 16 + g + rr * 8;
            float m = red[rowl * 16];
#pragma unroll
            for (int w = 1; w < 16; w++) m = fmaxf(m, red[rowl * 16 + w]);
            mrow[it][rr] = m;
        }
    __syncthreads();

    // ---- exp + row sum ----
#pragma unroll
    for (int it = 0; it < 2; it++)
#pragma unroll
        for (int rr = 0; rr < 2; rr++) {
            float s = 0.f;
#pragma unroll
            for (int jt = 0; jt < 8; jt++) {
                float p0 = __expf(acc[it][jt][rr * 2]     - mrow[it][rr]);
                float p1 = __expf(acc[it][jt][rr * 2 + 1] - mrow[it][rr]);
                acc[it][jt][rr * 2]     = p0;
                acc[it][jt][rr * 2 + 1] = p1;
                s += p0 + p1;
            }
            s += __shfl_xor_sync(0xffffffffu, s, 1);
            s += __shfl_xor_sync(0xffffffffu, s, 2);
            if (tig == 0) red[(it * 16 + g + rr * 8) * 16 + warp] = s;
        }
    __syncthreads();

    unsigned* Pb = d_Ph + ((size_t)b * LDIM + i0) * (LDIM / 2);
#pragma unroll
    for (int it = 0; it < 2; it++)
#pragma unroll
        for (int rr = 0; rr < 2; rr++) {
            int rowl = it * 16 + g + rr * 8;
            float s = red[rowl * 16];
#pragma unroll
            for (int w = 1; w < 16; w++) s += red[rowl * 16 + w];
            float inv = 1.0f / s;
            unsigned* prow = Pb + (size_t)rowl * (LDIM / 2) + j0w / 2 + tig;
#pragma unroll
            for (int jt = 0; jt < 8; jt++) {
                __half2 h = __floats2half2_rn(acc[it][jt][rr * 2] * inv,
                                              acc[it][jt][rr * 2 + 1] * inv);
                prow[jt * 4] = *reinterpret_cast<unsigned*>(&h);
            }
        }
}

// ---------------------------------------------------------------------------
// Kernel 2: V = P @ v^T, SD = P @ std^T  — EXACT R8 version (426 us best).
// CTA tile: 128i x 128c, 512 threads = 16 warps (4 wi x 4 wc), j chunk 64.
// Double-buffered cp.async, stage at loop bottom, 2 syncs/chunk.
// ---------------------------------------------------------------------------
#define T2  512
#define OSW 36   // uints per smem row (144 B)

#define OC_PS(buf)  ((buf) * (3 * 128 * OSW * 4))
#define OC_VS(buf)  (OC_PS(buf) + 128 * OSW * 4)
#define OC_SS(buf)  (OC_PS(buf) + 2 * 128 * OSW * 4)
#define OC_TOTAL    (2 * 3 * 128 * OSW * 4)

__global__ void __launch_bounds__(T2)
out_kernel(float* __restrict__ out) {
    extern __shared__ unsigned char smraw2[];
    const unsigned sbase = (unsigned)__cvta_generic_to_shared(smraw2);

    const int b    = blockIdx.z;
    const int i0   = blockIdx.x * 128;
    const int c0   = blockIdx.y * 128;
    const int tid  = threadIdx.x;
    const int warp = tid >> 5;
    const int lane = tid & 31;
    const int g    = lane >> 2;
    const int tig  = lane & 3;
    const int wi   = warp & 3;
    const int wc   = warp >> 2;

    const unsigned* Pb = d_Ph + ((size_t)b * LDIM + i0) * (LDIM / 2);
    const unsigned* vb = d_vpk + ((size_t)b * CDIM + c0) * (LDIM / 2);
    const unsigned* sb = d_spk + ((size_t)b * CDIM + c0) * (LDIM / 2);

    float aV[2][4][4], aS[2][4][4];
#pragma unroll
    for (int it = 0; it < 2; it++)
#pragma unroll
        for (int nt = 0; nt < 4; nt++)
#pragma unroll
            for (int f = 0; f < 4; f++) { aV[it][nt][f] = 0.f; aS[it][nt][f] = 0.f; }

#define OC_STAGE(JC, BUF)                                                     \
    {                                                                         \
        _Pragma("unroll")                                                     \
        for (int t = 0; t < 2; t++) {                                         \
            int idx  = tid + t * T2;                                          \
            int row  = idx >> 3;                                              \
            int col4 = idx & 7;                                               \
            unsigned soff = row * (OSW * 4) + col4 * 16;                      \
            size_t   goff = (size_t)row * (LDIM / 2) + (JC) * 32 + col4 * 4;  \
            cp16(sbase + OC_PS(BUF) + soff, Pb + goff);                       \
            cp16(sbase + OC_VS(BUF) + soff, vb + goff);                       \
            cp16(sbase + OC_SS(BUF) + soff, sb + goff);                       \
        }                                                                     \
        CP_COMMIT();                                                          \
    }

    OC_STAGE(0, 0);
    OC_STAGE(1, 1);

    const unsigned a_row = (lane & 15);
    const unsigned a_col = (lane >> 4) * 16;
    const unsigned b_row = ((lane >> 4) & 1) * 8 + (lane & 7);
    const unsigned b_col = ((lane >> 3) & 1) * 16;

    for (int jc = 0; jc < 16; jc++) {
        if (jc < 15) { CP_WAIT(1); } else { CP_WAIT(0); }
        __syncthreads();
        const int buf = jc & 1;

#pragma unroll
        for (int kb = 0; kb < 4; kb++) {
            unsigned a0[2], a1[2], a2[2], a3[2];
#pragma unroll
            for (int it = 0; it < 2; it++)
                ldsm4(a0[it], a1[it], a2[it], a3[it],
                      sbase + OC_PS(buf) +
                      (wi * 32 + it * 16 + a_row) * (OSW * 4) + kb * 32 + a_col);

            unsigned bv0[4], bv1[4], bs0[4], bs1[4];
#pragma unroll
            for (int nh = 0; nh < 2; nh++) {
                unsigned roff = (wc * 32 + nh * 16 + b_row) * (OSW * 4) + kb * 32 + b_col;
                ldsm4(bv0[2 * nh], bv1[2 * nh], bv0[2 * nh + 1], bv1[2 * nh + 1],
                      sbase + OC_VS(buf) + roff);
                ldsm4(bs0[2 * nh], bs1[2 * nh], bs0[2 * nh + 1], bs1[2 * nh + 1],
                      sbase + OC_SS(buf) + roff);
            }
#pragma unroll
            for (int nt = 0; nt < 4; nt++)
#pragma unroll
                for (int it = 0; it < 2; it++) {
                    mma16(aV[it][nt], a0[it], a1[it], a2[it], a3[it], bv0[nt], bv1[nt]);
                    mma16(aS[it][nt], a0[it], a1[it], a2[it], a3[it], bs0[nt], bs1[nt]);
                }
        }
        __syncthreads();
        if (jc + 2 < 16) OC_STAGE(jc + 2, buf);
    }

    const size_t base  = (size_t)b * CDIM * LDIM;
    const size_t sdoff = (size_t)BATCH * CDIM * LDIM;
#pragma unroll
    for (int it = 0; it < 2; it++)
#pragma unroll
        for (int nt = 0; nt < 4; nt++)
#pragma unroll
            for (int rr = 0; rr < 2; rr++) {
                int i = i0 + wi * 32 + it * 16 + g + rr * 8;
#pragma unroll
                for (int ff = 0; ff < 2; ff++) {
                    int c = c0 + wc * 32 + nt * 8 + 2 * tig + ff;
                    size_t o = base + (size_t)c * LDIM + i;
                    out[o]         = aV[it][nt][rr * 2 + ff];
                    out[o + sdoff] = aS[it][nt][rr * 2 + ff];
                }
            }
}

// ---------------------------------------------------------------------------
extern "C" void kernel_launch(void* const* d_in, const int* in_sizes, int n_in,
                              void* d_out, int out_size) {
    const float* q     = (const float*)d_in[0];
    const float* k     = (const float*)d_in[1];
    const float* v     = (const float*)d_in[2];
    const float* sd    = (const float*)d_in[3];
    const float* table = (const float*)d_in[4];
    const int*   ridx  = (const int*)d_in[5];
    float* out = (float*)d_out;

    cudaFuncSetAttribute(scores_kernel, cudaFuncAttributeMaxDynamicSharedMemorySize, SC_TOTAL);
    cudaFuncSetAttribute(out_kernel,    cudaFuncAttributeMaxDynamicSharedMemorySize, OC_TOTAL);

    pack_q  <<<(BATCH * (CDIM / 2) * LDIM) / 256, 256>>>(q);
    pack_kvs<<<(BATCH * CDIM * (LDIM / 2)) / 256, 256>>>(k, v, sd);
    bias_kernel<<<(LDIM * LDIM) / 256, 256>>>(table, ridx);
    scores_kernel<<<dim3(LDIM / 32, BATCH), T1, SC_TOTAL>>>();
    out_kernel<<<dim3(LDIM / 128, CDIM / 128, BATCH), T2, OC_TOTAL>>>(out);
}

// round 11
// speedup vs baseline: 1.5663x; 1.2710x over previous
#include <cuda_runtime.h>
#include <cuda_fp16.h>

#define BATCH 32
#define CDIM  256
#define LDIM  1024

// ---------------------------------------------------------------------------
// Global scratch (pair-packed fp16 operands + half2 P + dense bias)  [R8 layout]
// q/k packed: [b][m][i], m = c/2, uint2 = (hi2, lo2)
// v/std packed: [b][c][j2] half2 ; P: [b][i][j2] half2 ; bias dense fp32
// ---------------------------------------------------------------------------
__device__ uint2    d_qpk[(size_t)BATCH * (CDIM / 2) * LDIM];      // 32 MiB
__device__ uint2    d_kpk[(size_t)BATCH * (CDIM / 2) * LDIM];      // 32 MiB
__device__ unsigned d_vpk[(size_t)BATCH * CDIM * (LDIM / 2)];      // 16 MiB
__device__ unsigned d_spk[(size_t)BATCH * CDIM * (LDIM / 2)];      // 16 MiB
__device__ unsigned d_Ph [(size_t)BATCH * LDIM * (LDIM / 2)];      // 64 MiB
__device__ float    d_bias[(size_t)LDIM * LDIM];                   //  4 MiB

__device__ __forceinline__ unsigned pk2(__half a, __half b) {
    __half2 t = __halves2half2(a, b);
    return *reinterpret_cast<unsigned*>(&t);
}

__device__ __forceinline__ void mma16(float* c,
                                      unsigned a0, unsigned a1, unsigned a2, unsigned a3,
                                      unsigned b0, unsigned b1) {
    asm volatile(
        "mma.sync.aligned.m16n8k16.row.col.f32.f16.f16.f32 "
        "{%0,%1,%2,%3}, {%4,%5,%6,%7}, {%8,%9}, {%0,%1,%2,%3};\n"
        : "+f"(c[0]), "+f"(c[1]), "+f"(c[2]), "+f"(c[3])
        : "r"(a0), "r"(a1), "r"(a2), "r"(a3), "r"(b0), "r"(b1));
}

__device__ __forceinline__ void ldsm4(unsigned& r0, unsigned& r1,
                                      unsigned& r2, unsigned& r3, unsigned a) {
    asm volatile("ldmatrix.sync.aligned.m8n8.x4.shared.b16 {%0,%1,%2,%3}, [%4];"
                 : "=r"(r0), "=r"(r1), "=r"(r2), "=r"(r3) : "r"(a));
}

__device__ __forceinline__ void cp16(unsigned dst, const void* src) {
    asm volatile("cp.async.cg.shared.global [%0], [%1], 16;" :: "r"(dst), "l"(src));
}
#define CP_COMMIT() asm volatile("cp.async.commit_group;")
#define CP_WAIT(N)  asm volatile("cp.async.wait_group %0;" :: "n"(N))

// ---------------------------------------------------------------------------
// Pack kernels (R8 versions)
// ---------------------------------------------------------------------------
__global__ void pack_qk(const float* __restrict__ q, const float* __restrict__ k) {
    int gid = blockIdx.x * 256 + threadIdx.x;
    int b   = gid >> 17;
    int rem = gid & 131071;
    int m   = rem >> 10;
    int i   = rem & 1023;
    size_t src = (size_t)b * CDIM * LDIM + (size_t)(2 * m) * LDIM + i;

    float x0 = q[src], x1 = q[src + LDIM];
    __half h0 = __float2half_rn(x0), h1 = __float2half_rn(x1);
    __half l0 = __float2half_rn(x0 - __half2float(h0));
    __half l1 = __float2half_rn(x1 - __half2float(h1));
    d_qpk[gid] = make_uint2(pk2(h0, h1), pk2(l0, l1));

    float y0 = k[src], y1 = k[src + LDIM];
    __half g0 = __float2half_rn(y0), g1 = __float2half_rn(y1);
    __half m0 = __float2half_rn(y0 - __half2float(g0));
    __half m1 = __float2half_rn(y1 - __half2float(g1));
    d_kpk[gid] = make_uint2(pk2(g0, g1), pk2(m0, m1));
}

__global__ void pack_vs(const float* __restrict__ v, const float* __restrict__ sd) {
    int gid = blockIdx.x * 256 + threadIdx.x;
    size_t src = (size_t)gid * 2;
    float2 t = *(const float2*)(v + src);
    d_vpk[gid] = pk2(__float2half_rn(t.x), __float2half_rn(t.y));
    float2 u = *(const float2*)(sd + src);
    d_spk[gid] = pk2(__float2half_rn(u.x), __float2half_rn(u.y));
}

__global__ void bias_kernel(const float* __restrict__ table,
                            const int* __restrict__ ridx) {
    int i = blockIdx.x * blockDim.x + threadIdx.x;
    d_bias[i] = table[ridx[i]];
}

// ---------------------------------------------------------------------------
// Kernel 1: scores = Q^T K + bias (fp16x2 3-pass), softmax, P -> half2.
// EXACT R8 version (245 us).
// ---------------------------------------------------------------------------
#define T1  512
#define KS2 1028
#define QSW 12

#define SC_KS(buf)   ((buf) * (8 * KS2 * 8))
#define SC_QH(buf)   (2 * 8 * KS2 * 8 + (buf) * (32 * QSW * 4))
#define SC_QL(buf)   (2 * 8 * KS2 * 8 + 2 * (32 * QSW * 4) + (buf) * (32 * QSW * 4))
#define SC_RED       (2 * 8 * KS2 * 8 + 4 * (32 * QSW * 4))
#define SC_TOTAL     (SC_RED + 32 * 16 * 4)

__global__ void __launch_bounds__(T1)
scores_kernel(void) {
    extern __shared__ unsigned char smraw[];
    const unsigned sbase = (unsigned)__cvta_generic_to_shared(smraw);

    const int b    = blockIdx.y;
    const int i0   = blockIdx.x * 32;
    const int tid  = threadIdx.x;
    const int warp = tid >> 5;
    const int lane = tid & 31;
    const int g    = lane >> 2;
    const int tig  = lane & 3;
    const int j0w  = warp * 64;

    const uint2* gq = d_qpk + (size_t)b * (CDIM / 2) * LDIM;
    const uint2* gk = d_kpk + (size_t)b * (CDIM / 2) * LDIM;

    float acc[2][8][4];
#pragma unroll
    for (int it = 0; it < 2; it++)
#pragma unroll
        for (int jt = 0; jt < 8; jt++)
#pragma unroll
            for (int f = 0; f < 4; f++) acc[it][jt][f] = 0.f;

#define SC_STAGE(CC, BUF)                                                     \
    {                                                                         \
        const uint4* src4 = (const uint4*)(gk + (size_t)(CC) * 8 * LDIM);     \
        unsigned ksb = sbase + SC_KS(BUF);                                    \
        _Pragma("unroll")                                                     \
        for (int t = 0; t < 8; t++) {                                         \
            int idx  = tid + t * T1;                                          \
            int row  = idx >> 9;                                              \
            int col4 = idx & 511;                                             \
            cp16(ksb + row * (KS2 * 8) + col4 * 16, src4 + idx);              \
        }                                                                     \
        if (tid < 256) {                                                      \
            int m = tid >> 5, ii = tid & 31;                                  \
            uint2 qv = gq[(size_t)((CC) * 8 + m) * LDIM + i0 + ii];           \
            *(unsigned*)(smraw + SC_QH(BUF) + (ii * QSW + m) * 4) = qv.x;     \
            *(unsigned*)(smraw + SC_QL(BUF) + (ii * QSW + m) * 4) = qv.y;     \
        }                                                                     \
        CP_COMMIT();                                                          \
    }

    SC_STAGE(0, 0);
    SC_STAGE(1, 1);

    for (int cc = 0; cc < 16; cc++) {
        if (cc < 15) { CP_WAIT(1); } else { CP_WAIT(0); }
        __syncthreads();

        const int buf = cc & 1;
        unsigned ah[2][4], al[2][4];
        const unsigned arow = (lane & 15);
        const unsigned acol = (lane >> 4) * 16;
#pragma unroll
        for (int it = 0; it < 2; it++) {
            ldsm4(ah[it][0], ah[it][1], ah[it][2], ah[it][3],
                  sbase + SC_QH(buf) + (it * 16 + arow) * (QSW * 4) + acol);
            ldsm4(al[it][0], al[it][1], al[it][2], al[it][3],
                  sbase + SC_QL(buf) + (it * 16 + arow) * (QSW * 4) + acol);
        }
        const uint2* ksb = (const uint2*)(smraw + SC_KS(buf));
#pragma unroll
        for (int jh = 0; jh < 2; jh++) {
            uint2 y0[4], y1[4];
#pragma unroll
            for (int j4 = 0; j4 < 4; j4++) {
                int jcol = j0w + (jh * 4 + j4) * 8 + g;
                y0[j4] = ksb[tig * KS2 + jcol];
                y1[j4] = ksb[(tig + 4) * KS2 + jcol];
            }
            // pass 1: hi*hi
#pragma unroll
            for (int j4 = 0; j4 < 4; j4++)
#pragma unroll
                for (int it = 0; it < 2; it++)
                    mma16(acc[it][jh * 4 + j4], ah[it][0], ah[it][1], ah[it][2], ah[it][3],
                          y0[j4].x, y1[j4].x);
            // pass 2: hi*lo
#pragma unroll
            for (int j4 = 0; j4 < 4; j4++)
#pragma unroll
                for (int it = 0; it < 2; it++)
                    mma16(acc[it][jh * 4 + j4], ah[it][0], ah[it][1], ah[it][2], ah[it][3],
                          y0[j4].y, y1[j4].y);
            // pass 3: lo*hi
#pragma unroll
            for (int j4 = 0; j4 < 4; j4++)
#pragma unroll
                for (int it = 0; it < 2; it++)
                    mma16(acc[it][jh * 4 + j4], al[it][0], al[it][1], al[it][2], al[it][3],
                          y0[j4].x, y1[j4].x);
        }
        __syncthreads();
        if (cc + 2 < 16) SC_STAGE(cc + 2, buf);
    }

    float* red = (float*)(smraw + SC_RED);

    // ---- add bias ----
#pragma unroll
    for (int it = 0; it < 2; it++)
#pragma unroll
        for (int rr = 0; rr < 2; rr++) {
            int rowl = it * 16 + g + rr * 8;
            const float* brow = d_bias + (size_t)(i0 + rowl) * LDIM + j0w + 2 * tig;
#pragma unroll
            for (int jt = 0; jt < 8; jt++) {
                float2 bv = *(const float2*)(brow + jt * 8);
                acc[it][jt][rr * 2]     += bv.x;
                acc[it][jt][rr * 2 + 1] += bv.y;
            }
        }

    // ---- row max ----
    float mrow[2][2];
#pragma unroll
    for (int it = 0; it < 2; it++)
#pragma unroll
        for (int rr = 0; rr < 2; rr++) {
            float m = -3.4e38f;
#pragma unroll
            for (int jt = 0; jt < 8; jt++) {
                m = fmaxf(m, acc[it][jt][rr * 2]);
                m = fmaxf(m, acc[it][jt][rr * 2 + 1]);
            }
            m = fmaxf(m, __shfl_xor_sync(0xffffffffu, m, 1));
            m = fmaxf(m, __shfl_xor_sync(0xffffffffu, m, 2));
            if (tig == 0) red[(it * 16 + g + rr * 8) * 16 + warp] = m;
        }
    __syncthreads();
#pragma unroll
    for (int it = 0; it < 2; it++)
#pragma unroll
        for (int rr = 0; rr < 2; rr++) {
            int rowl = it * 16 + g + rr * 8;
            float m = red[rowl * 16];
#pragma unroll
            for (int w = 1; w < 16; w++) m = fmaxf(m, red[rowl * 16 + w]);
            mrow[it][rr] = m;
        }
    __syncthreads();

    // ---- exp + row sum ----
#pragma unroll
    for (int it = 0; it < 2; it++)
#pragma unroll
        for (int rr = 0; rr < 2; rr++) {
            float s = 0.f;
#pragma unroll
            for (int jt = 0; jt < 8; jt++) {
                float p0 = __expf(acc[it][jt][rr * 2]     - mrow[it][rr]);
                float p1 = __expf(acc[it][jt][rr * 2 + 1] - mrow[it][rr]);
                acc[it][jt][rr * 2]     = p0;
                acc[it][jt][rr * 2 + 1] = p1;
                s += p0 + p1;
            }
            s += __shfl_xor_sync(0xffffffffu, s, 1);
            s += __shfl_xor_sync(0xffffffffu, s, 2);
            if (tig == 0) red[(it * 16 + g + rr * 8) * 16 + warp] = s;
        }
    __syncthreads();

    unsigned* Pb = d_Ph + ((size_t)b * LDIM + i0) * (LDIM / 2);
#pragma unroll
    for (int it = 0; it < 2; it++)
#pragma unroll
        for (int rr = 0; rr < 2; rr++) {
            int rowl = it * 16 + g + rr * 8;
            float s = red[rowl * 16];
#pragma unroll
            for (int w = 1; w < 16; w++) s += red[rowl * 16 + w];
            float inv = 1.0f / s;
            unsigned* prow = Pb + (size_t)rowl * (LDIM / 2) + j0w / 2 + tig;
#pragma unroll
            for (int jt = 0; jt < 8; jt++) {
                __half2 h = __floats2half2_rn(acc[it][jt][rr * 2] * inv,
                                              acc[it][jt][rr * 2 + 1] * inv);
                prow[jt * 4] = *reinterpret_cast<unsigned*>(&h);
            }
        }
}

// ---------------------------------------------------------------------------
// Kernel 2: V = P @ v^T, SD = P @ std^T — retiled for occupancy.
// CTA tile: 128i x 64c, 256 threads = 8 warps (4 wi x 2 wc), warp tile 32x32.
// grid (8, 4, 32) = 1024 CTAs (3.5 waves), 2 CTAs/SM (smem 73.7 KB, bounds 2).
// Inner loop identical to R8. Double-buffered cp.async, stage at bottom.
// ---------------------------------------------------------------------------
#define T2  256
#define OSW 36   // uints per smem row (144 B)

#define OC_BUFB     ((128 + 64 + 64) * OSW * 4)          // 36864 B per buffer
#define OC_PS(buf)  ((buf) * OC_BUFB)
#define OC_VS(buf)  (OC_PS(buf) + 128 * OSW * 4)
#define OC_SS(buf)  (OC_PS(buf) + (128 + 64) * OSW * 4)
#define OC_TOTAL    (2 * OC_BUFB)                        // 73728 B

__global__ void __launch_bounds__(T2, 2)
out_kernel(float* __restrict__ out) {
    extern __shared__ unsigned char smraw2[];
    const unsigned sbase = (unsigned)__cvta_generic_to_shared(smraw2);

    const int b    = blockIdx.z;
    const int i0   = blockIdx.x * 128;
    const int c0   = blockIdx.y * 64;
    const int tid  = threadIdx.x;
    const int warp = tid >> 5;
    const int lane = tid & 31;
    const int g    = lane >> 2;
    const int tig  = lane & 3;
    const int wi   = warp & 3;          // i block of 32 (4 blocks -> 128)
    const int wc   = warp >> 2;         // c block of 32 (2 blocks -> 64)

    const unsigned* Pb = d_Ph + ((size_t)b * LDIM + i0) * (LDIM / 2);
    const unsigned* vb = d_vpk + ((size_t)b * CDIM + c0) * (LDIM / 2);
    const unsigned* sb = d_spk + ((size_t)b * CDIM + c0) * (LDIM / 2);

    float aV[2][4][4], aS[2][4][4];
#pragma unroll
    for (int it = 0; it < 2; it++)
#pragma unroll
        for (int nt = 0; nt < 4; nt++)
#pragma unroll
            for (int f = 0; f < 4; f++) { aV[it][nt][f] = 0.f; aS[it][nt][f] = 0.f; }

#define OC_STAGE(JC, BUF)                                                     \
    {                                                                         \
        _Pragma("unroll")                                                     \
        for (int t = 0; t < 4; t++) {                                         \
            int idx  = tid + t * T2;                                          \
            int row  = idx >> 3;                                              \
            int col4 = idx & 7;                                               \
            cp16(sbase + OC_PS(BUF) + row * (OSW * 4) + col4 * 16,            \
                 Pb + (size_t)row * (LDIM / 2) + (JC) * 32 + col4 * 4);       \
        }                                                                     \
        _Pragma("unroll")                                                     \
        for (int t = 0; t < 2; t++) {                                         \
            int idx  = tid + t * T2;                                          \
            int row  = idx >> 3;                                              \
            int col4 = idx & 7;                                               \
            unsigned soff = row * (OSW * 4) + col4 * 16;                      \
            size_t   goff = (size_t)row * (LDIM / 2) + (JC) * 32 + col4 * 4;  \
            cp16(sbase + OC_VS(BUF) + soff, vb + goff);                       \
            cp16(sbase + OC_SS(BUF) + soff, sb + goff);                       \
        }                                                                     \
        CP_COMMIT();                                                          \
    }

    OC_STAGE(0, 0);
    OC_STAGE(1, 1);

    const unsigned a_row = (lane & 15);
    const unsigned a_col = (lane >> 4) * 16;
    const unsigned b_row = ((lane >> 4) & 1) * 8 + (lane & 7);
    const unsigned b_col = ((lane >> 3) & 1) * 16;

    for (int jc = 0; jc < 16; jc++) {
        if (jc < 15) { CP_WAIT(1); } else { CP_WAIT(0); }
        __syncthreads();
        const int buf = jc & 1;

#pragma unroll
        for (int kb = 0; kb < 4; kb++) {
            unsigned a0[2], a1[2], a2[2], a3[2];
#pragma unroll
            for (int it = 0; it < 2; it++)
                ldsm4(a0[it], a1[it], a2[it], a3[it],
                      sbase + OC_PS(buf) +
                      (wi * 32 + it * 16 + a_row) * (OSW * 4) + kb * 32 + a_col);

            unsigned bv0[4], bv1[4], bs0[4], bs1[4];
#pragma unroll
            for (int nh = 0; nh < 2; nh++) {
                unsigned roff = (wc * 32 + nh * 16 + b_row) * (OSW * 4) + kb * 32 + b_col;
                ldsm4(bv0[2 * nh], bv1[2 * nh], bv0[2 * nh + 1], bv1[2 * nh + 1],
                      sbase + OC_VS(buf) + roff);
                ldsm4(bs0[2 * nh], bs1[2 * nh], bs0[2 * nh + 1], bs1[2 * nh + 1],
                      sbase + OC_SS(buf) + roff);
            }
#pragma unroll
            for (int nt = 0; nt < 4; nt++)
#pragma unroll
                for (int it = 0; it < 2; it++) {
                    mma16(aV[it][nt], a0[it], a1[it], a2[it], a3[it], bv0[nt], bv1[nt]);
                    mma16(aS[it][nt], a0[it], a1[it], a2[it], a3[it], bs0[nt], bs1[nt]);
                }
        }
        __syncthreads();
        if (jc + 2 < 16) OC_STAGE(jc + 2, buf);
    }

    const size_t base  = (size_t)b * CDIM * LDIM;
    const size_t sdoff = (size_t)BATCH * CDIM * LDIM;
#pragma unroll
    for (int it = 0; it < 2; it++)
#pragma unroll
        for (int nt = 0; nt < 4; nt++)
#pragma unroll
            for (int rr = 0; rr < 2; rr++) {
                int i = i0 + wi * 32 + it * 16 + g + rr * 8;
#pragma unroll
                for (int ff = 0; ff < 2; ff++) {
                    int c = c0 + wc * 32 + nt * 8 + 2 * tig + ff;
                    size_t o = base + (size_t)c * LDIM + i;
                    out[o]         = aV[it][nt][rr * 2 + ff];
                    out[o + sdoff] = aS[it][nt][rr * 2 + ff];
                }
            }
}

// ---------------------------------------------------------------------------
extern "C" void kernel_launch(void* const* d_in, const int* in_sizes, int n_in,
                              void* d_out, int out_size) {
    const float* q     = (const float*)d_in[0];
    const float* k     = (const float*)d_in[1];
    const float* v     = (const float*)d_in[2];
    const float* sd    = (const float*)d_in[3];
    const float* table = (const float*)d_in[4];
    const int*   ridx  = (const int*)d_in[5];
    float* out = (float*)d_out;

    cudaFuncSetAttribute(scores_kernel, cudaFuncAttributeMaxDynamicSharedMemorySize, SC_TOTAL);
    cudaFuncSetAttribute(out_kernel,    cudaFuncAttributeMaxDynamicSharedMemorySize, OC_TOTAL);

    pack_qk<<<(BATCH * (CDIM / 2) * LDIM) / 256, 256>>>(q, k);
    pack_vs<<<(BATCH * CDIM * (LDIM / 2)) / 256, 256>>>(v, sd);
    bias_kernel<<<(LDIM * LDIM) / 256, 256>>>(table, ridx);
    scores_kernel<<<dim3(LDIM / 32, BATCH), T1, SC_TOTAL>>>();
    out_kernel<<<dim3(LDIM / 128, CDIM / 64, BATCH), T2, OC_TOTAL>>>(out);
}

// round 12
// speedup vs baseline: 1.8685x; 1.1929x over previous
#include <cuda_runtime.h>
#include <cuda_fp16.h>

#define BATCH 32
#define CDIM  256
#define LDIM  1024

// ---------------------------------------------------------------------------
// Global scratch (R8/R11 layouts)
// q/k packed: [b][m][i], m = c/2, uint2 = (hi2, lo2)
// v/std packed: [b][c][j2] half2 ; P: [b][i][j2] half2 ; bias dense fp32
// ---------------------------------------------------------------------------
__device__ uint2    d_qpk[(size_t)BATCH * (CDIM / 2) * LDIM];      // 32 MiB
__device__ uint2    d_kpk[(size_t)BATCH * (CDIM / 2) * LDIM];      // 32 MiB
__device__ unsigned d_vpk[(size_t)BATCH * CDIM * (LDIM / 2)];      // 16 MiB
__device__ unsigned d_spk[(size_t)BATCH * CDIM * (LDIM / 2)];      // 16 MiB
__device__ unsigned d_Ph [(size_t)BATCH * LDIM * (LDIM / 2)];      // 64 MiB
__device__ float    d_bias[(size_t)LDIM * LDIM];                   //  4 MiB

__device__ __forceinline__ unsigned pk2(__half a, __half b) {
    __half2 t = __halves2half2(a, b);
    return *reinterpret_cast<unsigned*>(&t);
}

__device__ __forceinline__ void mma16(float* c,
                                      unsigned a0, unsigned a1, unsigned a2, unsigned a3,
                                      unsigned b0, unsigned b1) {
    asm volatile(
        "mma.sync.aligned.m16n8k16.row.col.f32.f16.f16.f32 "
        "{%0,%1,%2,%3}, {%4,%5,%6,%7}, {%8,%9}, {%0,%1,%2,%3};\n"
        : "+f"(c[0]), "+f"(c[1]), "+f"(c[2]), "+f"(c[3])
        : "r"(a0), "r"(a1), "r"(a2), "r"(a3), "r"(b0), "r"(b1));
}

__device__ __forceinline__ void ldsm4(unsigned& r0, unsigned& r1,
                                      unsigned& r2, unsigned& r3, unsigned a) {
    asm volatile("ldmatrix.sync.aligned.m8n8.x4.shared.b16 {%0,%1,%2,%3}, [%4];"
                 : "=r"(r0), "=r"(r1), "=r"(r2), "=r"(r3) : "r"(a));
}

__device__ __forceinline__ void cp16(unsigned dst, const void* src) {
    asm volatile("cp.async.cg.shared.global [%0], [%1], 16;" :: "r"(dst), "l"(src));
}
__device__ __forceinline__ void cp4(unsigned dst, const void* src) {
    asm volatile("cp.async.ca.shared.global [%0], [%1], 4;" :: "r"(dst), "l"(src));
}
#define CP_COMMIT() asm volatile("cp.async.commit_group;")
#define CP_WAIT(N)  asm volatile("cp.async.wait_group %0;" :: "n"(N))

// ---------------------------------------------------------------------------
// Pack kernels (unchanged)
// ---------------------------------------------------------------------------
__global__ void pack_qk(const float* __restrict__ q, const float* __restrict__ k) {
    int gid = blockIdx.x * 256 + threadIdx.x;
    int b   = gid >> 17;
    int rem = gid & 131071;
    int m   = rem >> 10;
    int i   = rem & 1023;
    size_t src = (size_t)b * CDIM * LDIM + (size_t)(2 * m) * LDIM + i;

    float x0 = q[src], x1 = q[src + LDIM];
    __half h0 = __float2half_rn(x0), h1 = __float2half_rn(x1);
    __half l0 = __float2half_rn(x0 - __half2float(h0));
    __half l1 = __float2half_rn(x1 - __half2float(h1));
    d_qpk[gid] = make_uint2(pk2(h0, h1), pk2(l0, l1));

    float y0 = k[src], y1 = k[src + LDIM];
    __half g0 = __float2half_rn(y0), g1 = __float2half_rn(y1);
    __half m0 = __float2half_rn(y0 - __half2float(g0));
    __half m1 = __float2half_rn(y1 - __half2float(g1));
    d_kpk[gid] = make_uint2(pk2(g0, g1), pk2(m0, m1));
}

__global__ void pack_vs(const float* __restrict__ v, const float* __restrict__ sd) {
    int gid = blockIdx.x * 256 + threadIdx.x;
    size_t src = (size_t)gid * 2;
    float2 t = *(const float2*)(v + src);
    d_vpk[gid] = pk2(__float2half_rn(t.x), __float2half_rn(t.y));
    float2 u = *(const float2*)(sd + src);
    d_spk[gid] = pk2(__float2half_rn(u.x), __float2half_rn(u.y));
}

__global__ void bias_kernel(const float* __restrict__ table,
                            const int* __restrict__ ridx) {
    int i = blockIdx.x * blockDim.x + threadIdx.x;
    d_bias[i] = table[ridx[i]];
}

// ---------------------------------------------------------------------------
// Kernel 1: scores = Q^T K + bias (fp16x2 3-pass), softmax, P -> half2.
// BARRIER-FREE mainloop:
//  - full Q (hi/lo planes, [32 i][132-pad m]) staged ONCE; A frags ldsm resident.
//  - K staged warp-privately: warp w fetches its own 64-j slice per chunk into
//    its own double buffer (8 pair-rows x 68-pad uint2), per-warp cp.async
//    groups, NO __syncthreads between chunks.
// Inner mma structure identical to R8.
// ---------------------------------------------------------------------------
#define T1 512
// smem byte offsets
#define SC_QH   0                       // 32 * 132 * 4 = 16896
#define SC_QL   16896                   // 16896
#define SC_KW   33792                   // 16 warps * 2 bufs * 4352 = 139264
#define SC_RED  173056                  // 32 * 16 * 4 = 2048
#define SC_TOTAL 175104

__global__ void __launch_bounds__(T1)
scores_kernel(void) {
    extern __shared__ unsigned char smraw[];
    const unsigned sbase = (unsigned)__cvta_generic_to_shared(smraw);

    const int b    = blockIdx.y;
    const int i0   = blockIdx.x * 32;
    const int tid  = threadIdx.x;
    const int warp = tid >> 5;
    const int lane = tid & 31;
    const int g    = lane >> 2;
    const int tig  = lane & 3;
    const int j0w  = warp * 64;

    const uint2* gq = d_qpk + (size_t)b * (CDIM / 2) * LDIM;
    const uint2* gk = d_kpk + (size_t)b * (CDIM / 2) * LDIM;

    float acc[2][8][4];
#pragma unroll
    for (int it = 0; it < 2; it++)
#pragma unroll
        for (int jt = 0; jt < 8; jt++)
#pragma unroll
            for (int f = 0; f < 4; f++) acc[it][jt][f] = 0.f;

    // ---- stage full Q once: [i][m] planes, row pad 132 uints ----
#pragma unroll
    for (int t = 0; t < 8; t++) {
        int idx = tid + t * T1;
        int m   = idx >> 5;
        int ii  = idx & 31;
        const uint2* s = gq + (size_t)m * LDIM + i0 + ii;
        unsigned d = (unsigned)((ii * 132 + m) * 4);
        cp4(sbase + SC_QH + d, &s->x);
        cp4(sbase + SC_QL + d, &s->y);
    }
    CP_COMMIT();                          // group Gq

    // ---- per-warp K staging ----
    const int krow = lane >> 2;           // 0..7 pair-row
    const int kq4  = lane & 3;            // 16B quad
    const unsigned wkbase = sbase + SC_KW + warp * (2 * 4352);

#define SC_STAGEW(CC, BUF)                                                    \
    {                                                                         \
        unsigned dstb = wkbase + (BUF) * 4352 + krow * 544 + kq4 * 16;        \
        const uint2* srcb = gk + (size_t)((CC) * 8 + krow) * LDIM + j0w + kq4 * 2; \
        _Pragma("unroll")                                                     \
        for (int t = 0; t < 8; t++)                                           \
            cp16(dstb + t * 64, srcb + t * 8);                                \
        CP_COMMIT();                                                          \
    }

    SC_STAGEW(0, 0);                      // G0
    SC_STAGEW(1, 1);                      // G1
    CP_WAIT(2);                           // Q resident (G0/G1 may be in flight)
    __syncthreads();                      // the ONLY pre-epilogue barrier

    const unsigned arow = (lane & 15);
    const unsigned acol = (lane >> 4) * 16;
    const uint2* wkb0 = (const uint2*)(smraw + SC_KW + warp * (2 * 4352));
    const uint2* wkb1 = (const uint2*)(smraw + SC_KW + warp * (2 * 4352) + 4352);

    for (int cc = 0; cc < 16; cc++) {
        if (cc < 15) { CP_WAIT(1); } else { CP_WAIT(0); }

        // A fragments for this k16 from resident Q (m-block = cc, 32B per chunk)
        unsigned ah[2][4], al[2][4];
#pragma unroll
        for (int it = 0; it < 2; it++) {
            ldsm4(ah[it][0], ah[it][1], ah[it][2], ah[it][3],
                  sbase + SC_QH + (it * 16 + arow) * 528 + cc * 32 + acol);
            ldsm4(al[it][0], al[it][1], al[it][2], al[it][3],
                  sbase + SC_QL + (it * 16 + arow) * 528 + cc * 32 + acol);
        }

        const uint2* wkb = (cc & 1) ? wkb1 : wkb0;
        // jh = 0 : load y, mma
        uint2 y0a[4], y1a[4];
#pragma unroll
        for (int j4 = 0; j4 < 4; j4++) {
            int jcol = j4 * 8 + g;
            y0a[j4] = wkb[tig * 68 + jcol];
            y1a[j4] = wkb[(tig + 4) * 68 + jcol];
        }
#pragma unroll
        for (int j4 = 0; j4 < 4; j4++)
#pragma unroll
            for (int it = 0; it < 2; it++)
                mma16(acc[it][j4], ah[it][0], ah[it][1], ah[it][2], ah[it][3],
                      y0a[j4].x, y1a[j4].x);
#pragma unroll
        for (int j4 = 0; j4 < 4; j4++)
#pragma unroll
            for (int it = 0; it < 2; it++)
                mma16(acc[it][j4], ah[it][0], ah[it][1], ah[it][2], ah[it][3],
                      y0a[j4].y, y1a[j4].y);
#pragma unroll
        for (int j4 = 0; j4 < 4; j4++)
#pragma unroll
            for (int it = 0; it < 2; it++)
                mma16(acc[it][j4], al[it][0], al[it][1], al[it][2], al[it][3],
                      y0a[j4].x, y1a[j4].x);

        // jh = 1 : load y first, THEN refill this buffer (all reads issued
        // before any cp.async touches it), then mma.
        uint2 y0b[4], y1b[4];
#pragma unroll
        for (int j4 = 0; j4 < 4; j4++) {
            int jcol = 32 + j4 * 8 + g;
            y0b[j4] = wkb[tig * 68 + jcol];
            y1b[j4] = wkb[(tig + 4) * 68 + jcol];
        }
        if (cc + 2 < 16) SC_STAGEW(cc + 2, cc & 1);

#pragma unroll
        for (int j4 = 0; j4 < 4; j4++)
#pragma unroll
            for (int it = 0; it < 2; it++)
                mma16(acc[it][4 + j4], ah[it][0], ah[it][1], ah[it][2], ah[it][3],
                      y0b[j4].x, y1b[j4].x);
#pragma unroll
        for (int j4 = 0; j4 < 4; j4++)
#pragma unroll
            for (int it = 0; it < 2; it++)
                mma16(acc[it][4 + j4], ah[it][0], ah[it][1], ah[it][2], ah[it][3],
                      y0b[j4].y, y1b[j4].y);
#pragma unroll
        for (int j4 = 0; j4 < 4; j4++)
#pragma unroll
            for (int it = 0; it < 2; it++)
                mma16(acc[it][4 + j4], al[it][0], al[it][1], al[it][2], al[it][3],
                      y0b[j4].x, y1b[j4].x);
    }

    float* red = (float*)(smraw + SC_RED);

    // ---- add bias ----
#pragma unroll
    for (int it = 0; it < 2; it++)
#pragma unroll
        for (int rr = 0; rr < 2; rr++) {
            int rowl = it * 16 + g + rr * 8;
            const float* brow = d_bias + (size_t)(i0 + rowl) * LDIM + j0w + 2 * tig;
#pragma unroll
            for (int jt = 0; jt < 8; jt++) {
                float2 bv = *(const float2*)(brow + jt * 8);
                acc[it][jt][rr * 2]     += bv.x;
                acc[it][jt][rr * 2 + 1] += bv.y;
            }
        }

    // ---- row max ----
    float mrow[2][2];
#pragma unroll
    for (int it = 0; it < 2; it++)
#pragma unroll
        for (int rr = 0; rr < 2; rr++) {
            float m = -3.4e38f;
#pragma unroll
            for (int jt = 0; jt < 8; jt++) {
                m = fmaxf(m, acc[it][jt][rr * 2]);
                m = fmaxf(m, acc[it][jt][rr * 2 + 1]);
            }
            m = fmaxf(m, __shfl_xor_sync(0xffffffffu, m, 1));
            m = fmaxf(m, __shfl_xor_sync(0xffffffffu, m, 2));
            if (tig == 0) red[(it * 16 + g + rr * 8) * 16 + warp] = m;
        }
    __syncthreads();
#pragma unroll
    for (int it = 0; it < 2; it++)
#pragma unroll
        for (int rr = 0; rr < 2; rr++) {
            int rowl = it * 16 + g + rr * 8;
            float m = red[rowl * 16];
#pragma unroll
            for (int w = 1; w < 16; w++) m = fmaxf(m, red[rowl * 16 + w]);
            mrow[it][rr] = m;
        }
    __syncthreads();

    // ---- exp + row sum ----
#pragma unroll
    for (int it = 0; it < 2; it++)
#pragma unroll
        for (int rr = 0; rr < 2; rr++) {
            float s = 0.f;
#pragma unroll
            for (int jt = 0; jt < 8; jt++) {
                float p0 = __expf(acc[it][jt][rr * 2]     - mrow[it][rr]);
                float p1 = __expf(acc[it][jt][rr * 2 + 1] - mrow[it][rr]);
                acc[it][jt][rr * 2]     = p0;
                acc[it][jt][rr * 2 + 1] = p1;
                s += p0 + p1;
            }
            s += __shfl_xor_sync(0xffffffffu, s, 1);
            s += __shfl_xor_sync(0xffffffffu, s, 2);
            if (tig == 0) red[(it * 16 + g + rr * 8) * 16 + warp] = s;
        }
    __syncthreads();

    unsigned* Pb = d_Ph + ((size_t)b * LDIM + i0) * (LDIM / 2);
#pragma unroll
    for (int it = 0; it < 2; it++)
#pragma unroll
        for (int rr = 0; rr < 2; rr++) {
            int rowl = it * 16 + g + rr * 8;
            float s = red[rowl * 16];
#pragma unroll
            for (int w = 1; w < 16; w++) s += red[rowl * 16 + w];
            float inv = 1.0f / s;
            unsigned* prow = Pb + (size_t)rowl * (LDIM / 2) + j0w / 2 + tig;
#pragma unroll
            for (int jt = 0; jt < 8; jt++) {
                __half2 h = __floats2half2_rn(acc[it][jt][rr * 2] * inv,
                                              acc[it][jt][rr * 2 + 1] * inv);
                prow[jt * 4] = *reinterpret_cast<unsigned*>(&h);
            }
        }
}

// ---------------------------------------------------------------------------
// Kernel 2: EXACT R11 version (128i x 64c, 256 thr, 2 CTAs/SM).
// ---------------------------------------------------------------------------
#define T2  256
#define OSW 36

#define OC_BUFB     ((128 + 64 + 64) * OSW * 4)
#define OC_PS(buf)  ((buf) * OC_BUFB)
#define OC_VS(buf)  (OC_PS(buf) + 128 * OSW * 4)
#define OC_SS(buf)  (OC_PS(buf) + (128 + 64) * OSW * 4)
#define OC_TOTAL    (2 * OC_BUFB)

__global__ void __launch_bounds__(T2, 2)
out_kernel(float* __restrict__ out) {
    extern __shared__ unsigned char smraw2[];
    const unsigned sbase = (unsigned)__cvta_generic_to_shared(smraw2);

    const int b    = blockIdx.z;
    const int i0   = blockIdx.x * 128;
    const int c0   = blockIdx.y * 64;
    const int tid  = threadIdx.x;
    const int warp = tid >> 5;
    const int lane = tid & 31;
    const int g    = lane >> 2;
    const int tig  = lane & 3;
    const int wi   = warp & 3;
    const int wc   = warp >> 2;

    const unsigned* Pb = d_Ph + ((size_t)b * LDIM + i0) * (LDIM / 2);
    const unsigned* vb = d_vpk + ((size_t)b * CDIM + c0) * (LDIM / 2);
    const unsigned* sb = d_spk + ((size_t)b * CDIM + c0) * (LDIM / 2);

    float aV[2][4][4], aS[2][4][4];
#pragma unroll
    for (int it = 0; it < 2; it++)
#pragma unroll
        for (int nt = 0; nt < 4; nt++)
#pragma unroll
            for (int f = 0; f < 4; f++) { aV[it][nt][f] = 0.f; aS[it][nt][f] = 0.f; }

#define OC_STAGE(JC, BUF)                                                     \
    {                                                                         \
        _Pragma("unroll")                                                     \
        for (int t = 0; t < 4; t++) {                                         \
            int idx  = tid + t * T2;                                          \
            int row  = idx >> 3;                                              \
            int col4 = idx & 7;                                               \
            cp16(sbase + OC_PS(BUF) + row * (OSW * 4) + col4 * 16,            \
                 Pb + (size_t)row * (LDIM / 2) + (JC) * 32 + col4 * 4);       \
        }                                                                     \
        _Pragma("unroll")                                                     \
        for (int t = 0; t < 2; t++) {                                         \
            int idx  = tid + t * T2;                                          \
            int row  = idx >> 3;                                              \
            int col4 = idx & 7;                                               \
            unsigned soff = row * (OSW * 4) + col4 * 16;                      \
            size_t   goff = (size_t)row * (LDIM / 2) + (JC) * 32 + col4 * 4;  \
            cp16(sbase + OC_VS(BUF) + soff, vb + goff);                       \
            cp16(sbase + OC_SS(BUF) + soff, sb + goff);                       \
        }                                                                     \
        CP_COMMIT();                                                          \
    }

    OC_STAGE(0, 0);
    OC_STAGE(1, 1);

    const unsigned a_row = (lane & 15);
    const unsigned a_col = (lane >> 4) * 16;
    const unsigned b_row = ((lane >> 4) & 1) * 8 + (lane & 7);
    const unsigned b_col = ((lane >> 3) & 1) * 16;

    for (int jc = 0; jc < 16; jc++) {
        if (jc < 15) { CP_WAIT(1); } else { CP_WAIT(0); }
        __syncthreads();
        const int buf = jc & 1;

#pragma unroll
        for (int kb = 0; kb < 4; kb++) {
            unsigned a0[2], a1[2], a2[2], a3[2];
#pragma unroll
            for (int it = 0; it < 2; it++)
                ldsm4(a0[it], a1[it], a2[it], a3[it],
                      sbase + OC_PS(buf) +
                      (wi * 32 + it * 16 + a_row) * (OSW * 4) + kb * 32 + a_col);

            unsigned bv0[4], bv1[4], bs0[4], bs1[4];
#pragma unroll
            for (int nh = 0; nh < 2; nh++) {
                unsigned roff = (wc * 32 + nh * 16 + b_row) * (OSW * 4) + kb * 32 + b_col;
                ldsm4(bv0[2 * nh], bv1[2 * nh], bv0[2 * nh + 1], bv1[2 * nh + 1],
                      sbase + OC_VS(buf) + roff);
                ldsm4(bs0[2 * nh], bs1[2 * nh], bs0[2 * nh + 1], bs1[2 * nh + 1],
                      sbase + OC_SS(buf) + roff);
            }
#pragma unroll
            for (int nt = 0; nt < 4; nt++)
#pragma unroll
                for (int it = 0; it < 2; it++) {
                    mma16(aV[it][nt], a0[it], a1[it], a2[it], a3[it], bv0[nt], bv1[nt]);
                    mma16(aS[it][nt], a0[it], a1[it], a2[it], a3[it], bs0[nt], bs1[nt]);
                }
        }
        __syncthreads();
        if (jc + 2 < 16) OC_STAGE(jc + 2, buf);
    }

    const size_t base  = (size_t)b * CDIM * LDIM;
    const size_t sdoff = (size_t)BATCH * CDIM * LDIM;
#pragma unroll
    for (int it = 0; it < 2; it++)
#pragma unroll
        for (int nt = 0; nt < 4; nt++)
#pragma unroll
            for (int rr = 0; rr < 2; rr++) {
                int i = i0 + wi * 32 + it * 16 + g + rr * 8;
#pragma unroll
                for (int ff = 0; ff < 2; ff++) {
                    int c = c0 + wc * 32 + nt * 8 + 2 * tig + ff;
                    size_t o = base + (size_t)c * LDIM + i;
                    out[o]         = aV[it][nt][rr * 2 + ff];
                    out[o + sdoff] = aS[it][nt][rr * 2 + ff];
                }
            }
}

// ---------------------------------------------------------------------------
extern "C" void kernel_launch(void* const* d_in, const int* in_sizes, int n_in,
                              void* d_out, int out_size) {
    const float* q     = (const float*)d_in[0];
    const float* k     = (const float*)d_in[1];
    const float* v     = (const float*)d_in[2];
    const float* sd    = (const float*)d_in[3];
    const float* table = (const float*)d_in[4];
    const int*   ridx  = (const int*)d_in[5];
    float* out = (float*)d_out;

    cudaFuncSetAttribute(scores_kernel, cudaFuncAttributeMaxDynamicSharedMemorySize, SC_TOTAL);
    cudaFuncSetAttribute(out_kernel,    cudaFuncAttributeMaxDynamicSharedMemorySize, OC_TOTAL);

    pack_qk<<<(BATCH * (CDIM / 2) * LDIM) / 256, 256>>>(q, k);
    pack_vs<<<(BATCH * CDIM * (LDIM / 2)) / 256, 256>>>(v, sd);
    bias_kernel<<<(LDIM * LDIM) / 256, 256>>>(table, ridx);
    scores_kernel<<<dim3(LDIM / 32, BATCH), T1, SC_TOTAL>>>();
    out_kernel<<<dim3(LDIM / 128, CDIM / 64, BATCH), T2, OC_TOTAL>>>(out);
}

// round 13
// speedup vs baseline: 2.0268x; 1.0847x over previous
#include <cuda_runtime.h>
#include <cuda_fp16.h>

#define BATCH 32
#define CDIM  256
#define LDIM  1024

// ---------------------------------------------------------------------------
// Global scratch
// q/k packed: [b][m][i], m = c/2, uint2 = (hi2, lo2)
// v/std packed: [b][c][j2] half2 ; P: [b][i][j2] half2
// ---------------------------------------------------------------------------
__device__ uint2    d_qpk[(size_t)BATCH * (CDIM / 2) * LDIM];      // 32 MiB
__device__ uint2    d_kpk[(size_t)BATCH * (CDIM / 2) * LDIM];      // 32 MiB
__device__ unsigned d_vpk[(size_t)BATCH * CDIM * (LDIM / 2)];      // 16 MiB
__device__ unsigned d_spk[(size_t)BATCH * CDIM * (LDIM / 2)];      // 16 MiB
__device__ unsigned d_Ph [(size_t)BATCH * LDIM * (LDIM / 2)];      // 64 MiB

__device__ __forceinline__ unsigned pk2(__half a, __half b) {
    __half2 t = __halves2half2(a, b);
    return *reinterpret_cast<unsigned*>(&t);
}

__device__ __forceinline__ void mma16(float* c,
                                      unsigned a0, unsigned a1, unsigned a2, unsigned a3,
                                      unsigned b0, unsigned b1) {
    asm volatile(
        "mma.sync.aligned.m16n8k16.row.col.f32.f16.f16.f32 "
        "{%0,%1,%2,%3}, {%4,%5,%6,%7}, {%8,%9}, {%0,%1,%2,%3};\n"
        : "+f"(c[0]), "+f"(c[1]), "+f"(c[2]), "+f"(c[3])
        : "r"(a0), "r"(a1), "r"(a2), "r"(a3), "r"(b0), "r"(b1));
}

__device__ __forceinline__ void ldsm4(unsigned& r0, unsigned& r1,
                                      unsigned& r2, unsigned& r3, unsigned a) {
    asm volatile("ldmatrix.sync.aligned.m8n8.x4.shared.b16 {%0,%1,%2,%3}, [%4];"
                 : "=r"(r0), "=r"(r1), "=r"(r2), "=r"(r3) : "r"(a));
}

__device__ __forceinline__ void cp16(unsigned dst, const void* src) {
    asm volatile("cp.async.cg.shared.global [%0], [%1], 16;" :: "r"(dst), "l"(src));
}
__device__ __forceinline__ void cp4(unsigned dst, const void* src) {
    asm volatile("cp.async.ca.shared.global [%0], [%1], 4;" :: "r"(dst), "l"(src));
}
#define CP_COMMIT() asm volatile("cp.async.commit_group;")
#define CP_WAIT(N)  asm volatile("cp.async.wait_group %0;" :: "n"(N))

// ---------------------------------------------------------------------------
// Merged pack kernel: q/k hi-lo split pack + v/std pack, one gid space (4.19M)
// ---------------------------------------------------------------------------
__global__ void pack_all(const float* __restrict__ q, const float* __restrict__ k,
                         const float* __restrict__ v, const float* __restrict__ sd) {
    int gid = blockIdx.x * 256 + threadIdx.x;

    // ---- q/k: gid -> [b][m][i] ----
    {
        int b   = gid >> 17;
        int rem = gid & 131071;
        int m   = rem >> 10;
        int i   = rem & 1023;
        size_t src = (size_t)b * CDIM * LDIM + (size_t)(2 * m) * LDIM + i;

        float x0 = q[src], x1 = q[src + LDIM];
        __half h0 = __float2half_rn(x0), h1 = __float2half_rn(x1);
        __half l0 = __float2half_rn(x0 - __half2float(h0));
        __half l1 = __float2half_rn(x1 - __half2float(h1));
        d_qpk[gid] = make_uint2(pk2(h0, h1), pk2(l0, l1));

        float y0 = k[src], y1 = k[src + LDIM];
        __half g0 = __float2half_rn(y0), g1 = __float2half_rn(y1);
        __half m0 = __float2half_rn(y0 - __half2float(g0));
        __half m1 = __float2half_rn(y1 - __half2float(g1));
        d_kpk[gid] = make_uint2(pk2(g0, g1), pk2(m0, m1));
    }

    // ---- v/std: gid -> [b][c][j2] ----
    {
        size_t src = (size_t)gid * 2;
        float2 t = *(const float2*)(v + src);
        d_vpk[gid] = pk2(__float2half_rn(t.x), __float2half_rn(t.y));
        float2 u = *(const float2*)(sd + src);
        d_spk[gid] = pk2(__float2half_rn(u.x), __float2half_rn(u.y));
    }
}

// ---------------------------------------------------------------------------
// Kernel 1: scores = Q^T K + bias (fp16x2 3-pass), softmax, P -> half2.
// R12 barrier-free mainloop, unchanged except:
//  - carried K gmem pointer (less per-stage ALU)
//  - bias applied in epilogue via table[ridx] gather (bias kernel removed)
// ---------------------------------------------------------------------------
#define T1 512
#define SC_QH   0
#define SC_QL   16896
#define SC_KW   33792
#define SC_RED  173056
#define SC_TOTAL 175104

__global__ void __launch_bounds__(T1)
scores_kernel(const float* __restrict__ table, const int* __restrict__ ridx) {
    extern __shared__ unsigned char smraw[];
    const unsigned sbase = (unsigned)__cvta_generic_to_shared(smraw);

    const int b    = blockIdx.y;
    const int i0   = blockIdx.x * 32;
    const int tid  = threadIdx.x;
    const int warp = tid >> 5;
    const int lane = tid & 31;
    const int g    = lane >> 2;
    const int tig  = lane & 3;
    const int j0w  = warp * 64;

    const uint2* gq = d_qpk + (size_t)b * (CDIM / 2) * LDIM;
    const uint2* gk = d_kpk + (size_t)b * (CDIM / 2) * LDIM;

    float acc[2][8][4];
#pragma unroll
    for (int it = 0; it < 2; it++)
#pragma unroll
        for (int jt = 0; jt < 8; jt++)
#pragma unroll
            for (int f = 0; f < 4; f++) acc[it][jt][f] = 0.f;

    // ---- stage full Q once: [i][m] planes, row pad 132 uints ----
#pragma unroll
    for (int t = 0; t < 8; t++) {
        int idx = tid + t * T1;
        int m   = idx >> 5;
        int ii  = idx & 31;
        const uint2* s = gq + (size_t)m * LDIM + i0 + ii;
        unsigned d = (unsigned)((ii * 132 + m) * 4);
        cp4(sbase + SC_QH + d, &s->x);
        cp4(sbase + SC_QL + d, &s->y);
    }
    CP_COMMIT();

    // ---- per-warp K staging, carried pointer ----
    const int krow = lane >> 2;
    const int kq4  = lane & 3;
    const unsigned wd0 = sbase + SC_KW + warp * (2 * 4352) + krow * 544 + kq4 * 16;
    const unsigned wd1 = wd0 + 4352;
    const uint2* kptr = gk + (size_t)krow * LDIM + j0w + kq4 * 2;

#define SC_STAGEW(PTR, DSTB)                                                  \
    {                                                                         \
        _Pragma("unroll")                                                     \
        for (int t = 0; t < 8; t++)                                           \
            cp16((DSTB) + t * 64, (PTR) + t * 8);                             \
        CP_COMMIT();                                                          \
    }

    SC_STAGEW(kptr, wd0); kptr += 8 * LDIM;
    SC_STAGEW(kptr, wd1); kptr += 8 * LDIM;
    CP_WAIT(2);                           // Q resident
    __syncthreads();                      // the ONLY pre-epilogue barrier

    const unsigned arow = (lane & 15);
    const unsigned acol = (lane >> 4) * 16;
    const uint2* wkb0 = (const uint2*)(smraw + SC_KW + warp * (2 * 4352));
    const uint2* wkb1 = (const uint2*)(smraw + SC_KW + warp * (2 * 4352) + 4352);

    for (int cc = 0; cc < 16; cc++) {
        if (cc < 15) { CP_WAIT(1); } else { CP_WAIT(0); }

        unsigned ah[2][4], al[2][4];
#pragma unroll
        for (int it = 0; it < 2; it++) {
            ldsm4(ah[it][0], ah[it][1], ah[it][2], ah[it][3],
                  sbase + SC_QH + (it * 16 + arow) * 528 + cc * 32 + acol);
            ldsm4(al[it][0], al[it][1], al[it][2], al[it][3],
                  sbase + SC_QL + (it * 16 + arow) * 528 + cc * 32 + acol);
        }

        const uint2* wkb = (cc & 1) ? wkb1 : wkb0;
        // jh = 0
        uint2 y0a[4], y1a[4];
#pragma unroll
        for (int j4 = 0; j4 < 4; j4++) {
            int jcol = j4 * 8 + g;
            y0a[j4] = wkb[tig * 68 + jcol];
            y1a[j4] = wkb[(tig + 4) * 68 + jcol];
        }
#pragma unroll
        for (int j4 = 0; j4 < 4; j4++)
#pragma unroll
            for (int it = 0; it < 2; it++)
                mma16(acc[it][j4], ah[it][0], ah[it][1], ah[it][2], ah[it][3],
                      y0a[j4].x, y1a[j4].x);
#pragma unroll
        for (int j4 = 0; j4 < 4; j4++)
#pragma unroll
            for (int it = 0; it < 2; it++)
                mma16(acc[it][j4], ah[it][0], ah[it][1], ah[it][2], ah[it][3],
                      y0a[j4].y, y1a[j4].y);
#pragma unroll
        for (int j4 = 0; j4 < 4; j4++)
#pragma unroll
            for (int it = 0; it < 2; it++)
                mma16(acc[it][j4], al[it][0], al[it][1], al[it][2], al[it][3],
                      y0a[j4].x, y1a[j4].x);

        // jh = 1: reads first, then refill this buffer, then mma
        uint2 y0b[4], y1b[4];
#pragma unroll
        for (int j4 = 0; j4 < 4; j4++) {
            int jcol = 32 + j4 * 8 + g;
            y0b[j4] = wkb[tig * 68 + jcol];
            y1b[j4] = wkb[(tig + 4) * 68 + jcol];
        }
        if (cc + 2 < 16) {
            unsigned dcur = (cc & 1) ? wd1 : wd0;
            SC_STAGEW(kptr, dcur);
            kptr += 8 * LDIM;
        }

#pragma unroll
        for (int j4 = 0; j4 < 4; j4++)
#pragma unroll
            for (int it = 0; it < 2; it++)
                mma16(acc[it][4 + j4], ah[it][0], ah[it][1], ah[it][2], ah[it][3],
                      y0b[j4].x, y1b[j4].x);
#pragma unroll
        for (int j4 = 0; j4 < 4; j4++)
#pragma unroll
            for (int it = 0; it < 2; it++)
                mma16(acc[it][4 + j4], ah[it][0], ah[it][1], ah[it][2], ah[it][3],
                      y0b[j4].y, y1b[j4].y);
#pragma unroll
        for (int j4 = 0; j4 < 4; j4++)
#pragma unroll
            for (int it = 0; it < 2; it++)
                mma16(acc[it][4 + j4], al[it][0], al[it][1], al[it][2], al[it][3],
                      y0b[j4].x, y1b[j4].x);
    }

    float* red = (float*)(smraw + SC_RED);

    // ---- add bias via table[ridx] gather (fp32, exact same math as before) ----
#pragma unroll
    for (int it = 0; it < 2; it++)
#pragma unroll
        for (int rr = 0; rr < 2; rr++) {
            int rowl = it * 16 + g + rr * 8;
            const int* rrow = ridx + (size_t)(i0 + rowl) * LDIM + j0w + 2 * tig;
#pragma unroll
            for (int jt = 0; jt < 8; jt++) {
                int2 rv = *(const int2*)(rrow + jt * 8);
                acc[it][jt][rr * 2]     += __ldg(table + rv.x);
                acc[it][jt][rr * 2 + 1] += __ldg(table + rv.y);
            }
        }

    // ---- row max ----
    float mrow[2][2];
#pragma unroll
    for (int it = 0; it < 2; it++)
#pragma unroll
        for (int rr = 0; rr < 2; rr++) {
            float m = -3.4e38f;
#pragma unroll
            for (int jt = 0; jt < 8; jt++) {
                m = fmaxf(m, acc[it][jt][rr * 2]);
                m = fmaxf(m, acc[it][jt][rr * 2 + 1]);
            }
            m = fmaxf(m, __shfl_xor_sync(0xffffffffu, m, 1));
            m = fmaxf(m, __shfl_xor_sync(0xffffffffu, m, 2));
            if (tig == 0) red[(it * 16 + g + rr * 8) * 16 + warp] = m;
        }
    __syncthreads();
#pragma unroll
    for (int it = 0; it < 2; it++)
#pragma unroll
        for (int rr = 0; rr < 2; rr++) {
            int rowl = it * 16 + g + rr * 8;
            float m = red[rowl * 16];
#pragma unroll
            for (int w = 1; w < 16; w++) m = fmaxf(m, red[rowl * 16 + w]);
            mrow[it][rr] = m;
        }
    __syncthreads();

    // ---- exp + row sum ----
#pragma unroll
    for (int it = 0; it < 2; it++)
#pragma unroll
        for (int rr = 0; rr < 2; rr++) {
            float s = 0.f;
#pragma unroll
            for (int jt = 0; jt < 8; jt++) {
                float p0 = __expf(acc[it][jt][rr * 2]     - mrow[it][rr]);
                float p1 = __expf(acc[it][jt][rr * 2 + 1] - mrow[it][rr]);
                acc[it][jt][rr * 2]     = p0;
                acc[it][jt][rr * 2 + 1] = p1;
                s += p0 + p1;
            }
            s += __shfl_xor_sync(0xffffffffu, s, 1);
            s += __shfl_xor_sync(0xffffffffu, s, 2);
            if (tig == 0) red[(it * 16 + g + rr * 8) * 16 + warp] = s;
        }
    __syncthreads();

    unsigned* Pb = d_Ph + ((size_t)b * LDIM + i0) * (LDIM / 2);
#pragma unroll
    for (int it = 0; it < 2; it++)
#pragma unroll
        for (int rr = 0; rr < 2; rr++) {
            int rowl = it * 16 + g + rr * 8;
            float s = red[rowl * 16];
#pragma unroll
            for (int w = 1; w < 16; w++) s += red[rowl * 16 + w];
            float inv = 1.0f / s;
            unsigned* prow = Pb + (size_t)rowl * (LDIM / 2) + j0w / 2 + tig;
#pragma unroll
            for (int jt = 0; jt < 8; jt++) {
                __half2 h = __floats2half2_rn(acc[it][jt][rr * 2] * inv,
                                              acc[it][jt][rr * 2 + 1] * inv);
                prow[jt * 4] = *reinterpret_cast<unsigned*>(&h);
            }
        }
}

// ---------------------------------------------------------------------------
// Kernel 2: V = P @ v^T, SD = P @ std^T — R11 tiling (128i x 64c, 256 thr,
// 2 CTAs/SM) with 3 buffers and ONE __syncthreads per chunk (stage stays at
// loop bottom, after all reads of the buffer being refilled).
// ---------------------------------------------------------------------------
#define T2  256
#define OSW 36

#define OC_BUFB     ((128 + 64 + 64) * OSW * 4)          // 36864 B per buffer
#define OC_PS(buf)  ((buf) * OC_BUFB)
#define OC_VS(buf)  (OC_PS(buf) + 128 * OSW * 4)
#define OC_SS(buf)  (OC_PS(buf) + (128 + 64) * OSW * 4)
#define OC_TOTAL    (3 * OC_BUFB)                        // 110592 B

__global__ void __launch_bounds__(T2, 2)
out_kernel(float* __restrict__ out) {
    extern __shared__ unsigned char smraw2[];
    const unsigned sbase = (unsigned)__cvta_generic_to_shared(smraw2);

    const int b    = blockIdx.z;
    const int i0   = blockIdx.x * 128;
    const int c0   = blockIdx.y * 64;
    const int tid  = threadIdx.x;
    const int warp = tid >> 5;
    const int lane = tid & 31;
    const int g    = lane >> 2;
    const int tig  = lane & 3;
    const int wi   = warp & 3;
    const int wc   = warp >> 2;

    const unsigned* Pb = d_Ph + ((size_t)b * LDIM + i0) * (LDIM / 2);
    const unsigned* vb = d_vpk + ((size_t)b * CDIM + c0) * (LDIM / 2);
    const unsigned* sb = d_spk + ((size_t)b * CDIM + c0) * (LDIM / 2);

    float aV[2][4][4], aS[2][4][4];
#pragma unroll
    for (int it = 0; it < 2; it++)
#pragma unroll
        for (int nt = 0; nt < 4; nt++)
#pragma unroll
            for (int f = 0; f < 4; f++) { aV[it][nt][f] = 0.f; aS[it][nt][f] = 0.f; }

#define OC_STAGE(JC, BUF)                                                     \
    {                                                                         \
        _Pragma("unroll")                                                     \
        for (int t = 0; t < 4; t++) {                                         \
            int idx  = tid + t * T2;                                          \
            int row  = idx >> 3;                                              \
            int col4 = idx & 7;                                               \
            cp16(sbase + OC_PS(BUF) + row * (OSW * 4) + col4 * 16,            \
                 Pb + (size_t)row * (LDIM / 2) + (JC) * 32 + col4 * 4);       \
        }                                                                     \
        _Pragma("unroll")                                                     \
        for (int t = 0; t < 2; t++) {                                         \
            int idx  = tid + t * T2;                                          \
            int row  = idx >> 3;                                              \
            int col4 = idx & 7;                                               \
            unsigned soff = row * (OSW * 4) + col4 * 16;                      \
            size_t   goff = (size_t)row * (LDIM / 2) + (JC) * 32 + col4 * 4;  \
            cp16(sbase + OC_VS(BUF) + soff, vb + goff);                       \
            cp16(sbase + OC_SS(BUF) + soff, sb + goff);                       \
        }                                                                     \
        CP_COMMIT();                                                          \
    }

    OC_STAGE(0, 0);
    OC_STAGE(1, 1);

    const unsigned a_row = (lane & 15);
    const unsigned a_col = (lane >> 4) * 16;
    const unsigned b_row = ((lane >> 4) & 1) * 8 + (lane & 7);
    const unsigned b_col = ((lane >> 3) & 1) * 16;

    int bufc = 0;   // buffer consumed this chunk
    int bufs = 2;   // buffer staged this chunk (for jc+2)
    for (int jc = 0; jc < 16; jc++) {
        if (jc < 15) { CP_WAIT(1); } else { CP_WAIT(0); }
        __syncthreads();   // single barrier per chunk

#pragma unroll
        for (int kb = 0; kb < 4; kb++) {
            unsigned a0[2], a1[2], a2[2], a3[2];
#pragma unroll
            for (int it = 0; it < 2; it++)
                ldsm4(a0[it], a1[it], a2[it], a3[it],
                      sbase + OC_PS(bufc) +
                      (wi * 32 + it * 16 + a_row) * (OSW * 4) + kb * 32 + a_col);

            unsigned bv0[4], bv1[4], bs0[4], bs1[4];
#pragma unroll
            for (int nh = 0; nh < 2; nh++) {
                unsigned roff = (wc * 32 + nh * 16 + b_row) * (OSW * 4) + kb * 32 + b_col;
                ldsm4(bv0[2 * nh], bv1[2 * nh], bv0[2 * nh + 1], bv1[2 * nh + 1],
                      sbase + OC_VS(bufc) + roff);
                ldsm4(bs0[2 * nh], bs1[2 * nh], bs0[2 * nh + 1], bs1[2 * nh + 1],
                      sbase + OC_SS(bufc) + roff);
            }
#pragma unroll
            for (int nt = 0; nt < 4; nt++)
#pragma unroll
                for (int it = 0; it < 2; it++) {
                    mma16(aV[it][nt], a0[it], a1[it], a2[it], a3[it], bv0[nt], bv1[nt]);
                    mma16(aS[it][nt], a0[it], a1[it], a2[it], a3[it], bs0[nt], bs1[nt]);
                }
        }
        if (jc + 2 < 16) OC_STAGE(jc + 2, bufs);
        bufc = (bufc == 2) ? 0 : bufc + 1;
        bufs = (bufs == 2) ? 0 : bufs + 1;
    }

    const size_t base  = (size_t)b * CDIM * LDIM;
    const size_t sdoff = (size_t)BATCH * CDIM * LDIM;
#pragma unroll
    for (int it = 0; it < 2; it++)
#pragma unroll
        for (int nt = 0; nt < 4; nt++)
#pragma unroll
            for (int rr = 0; rr < 2; rr++) {
                int i = i0 + wi * 32 + it * 16 + g + rr * 8;
#pragma unroll
                for (int ff = 0; ff < 2; ff++) {
                    int c = c0 + wc * 32 + nt * 8 + 2 * tig + ff;
                    size_t o = base + (size_t)c * LDIM + i;
                    out[o]         = aV[it][nt][rr * 2 + ff];
                    out[o + sdoff] = aS[it][nt][rr * 2 + ff];
                }
            }
}

// ---------------------------------------------------------------------------
extern "C" void kernel_launch(void* const* d_in, const int* in_sizes, int n_in,
                              void* d_out, int out_size) {
    const float* q     = (const float*)d_in[0];
    const float* k     = (const float*)d_in[1];
    const float* v     = (const float*)d_in[2];
    const float* sd    = (const float*)d_in[3];
    const float* table = (const float*)d_in[4];
    const int*   ridx  = (const int*)d_in[5];
    float* out = (float*)d_out;

    cudaFuncSetAttribute(scores_kernel, cudaFuncAttributeMaxDynamicSharedMemorySize, SC_TOTAL);
    cudaFuncSetAttribute(out_kernel,    cudaFuncAttributeMaxDynamicSharedMemorySize, OC_TOTAL);

    pack_all<<<(BATCH * (CDIM / 2) * LDIM) / 256, 256>>>(q, k, v, sd);
    scores_kernel<<<dim3(LDIM / 32, BATCH), T1, SC_TOTAL>>>(table, ridx);
    out_kernel<<<dim3(LDIM / 128, CDIM / 64, BATCH), T2, OC_TOTAL>>>(out);
}